// round 4
// baseline (speedup 1.0000x reference)
#include <cuda_runtime.h>
#include <cuda_bf16.h>
#include <cstdint>

#define B_  4
#define T_  4096
#define NH  16
#define NKV 8
#define D_  128
#define WIN 1024
#define BM  64
#define BN  64
#define NTHREADS 256

// shared memory layout (float offsets)
#define QS_OFF 0                 // Q tile: 64 x 128           = 8192 floats
#define VS_OFF 8192              // V tile: 64 x 128           = 8192 floats
#define KS_OFF 16384             // K pair-transposed: 64 x 66 float2 = 8448 floats
#define PS_OFF 16384             // P tile (64 x 76) ALIASES K buffer (4864 <= 8448)
#define SMEM_FLOATS (16384 + 8448)

typedef unsigned long long u64;

__device__ __forceinline__ void ffma2(u64 &d, u64 a, u64 b) {
    asm("fma.rn.f32x2 %0, %1, %2, %0;" : "+l"(d) : "l"(a), "l"(b));
}
__device__ __forceinline__ void fmul2(u64 &d, u64 s) {
    asm("mul.rn.f32x2 %0, %0, %1;" : "+l"(d) : "l"(s));
}
__device__ __forceinline__ u64 pack2(float x, float y) {
    u64 u; asm("mov.b64 %0, {%1, %2};" : "=l"(u) : "f"(x), "f"(y)); return u;
}
__device__ __forceinline__ float2 unpack2(u64 u) {
    float2 f; asm("mov.b64 {%0, %1}, %2;" : "=f"(f.x), "=f"(f.y) : "l"(u)); return f;
}

__global__ void __launch_bounds__(NTHREADS, 2)
swa_fp32_kernel(const float* __restrict__ Q, const float* __restrict__ K,
                const float* __restrict__ V, float* __restrict__ Out)
{
    extern __shared__ float smem[];
    float* qs = smem + QS_OFF;
    float* vs = smem + VS_OFF;
    float* ks = smem + KS_OFF;
    float* ps = smem + PS_OFF;

    const int tid = threadIdx.x;
    const int tx  = tid & 15;
    const int ty  = tid >> 4;
    const int m0  = blockIdx.x * BM;   // q-block start
    const int h   = blockIdx.y;        // q head
    const int bb  = blockIdx.z;        // batch
    const int kh  = h >> 1;            // GQA: 2 q heads per kv head

    const int r0  = ty * 4;            // my 4 S/O rows
    const int c0  = tx * 4;            // my 4 S cols
    const int c0v = tx * 8;            // my 8 O cols

    // ---- load Q tile (64 x 128) ----
    {
        const size_t qbase = ((size_t)(bb * T_ + m0) * NH + h) * D_;
        #pragma unroll
        for (int i = 0; i < 8; i++) {
            int idx = tid + i * NTHREADS;            // 2048 float4s
            int row = idx >> 5;
            int c4  = (idx & 31) << 2;
            float4 v4 = *(const float4*)(Q + qbase + (size_t)row * (NH * D_) + c4);
            *(float4*)(qs + row * D_ + c4) = v4;
        }
    }

    // output accumulators: 4 rows x 4 float2 (8 cols), packed f32x2
    u64 Oacc[4][4];
    #pragma unroll
    for (int i = 0; i < 4; i++)
        #pragma unroll
        for (int j = 0; j < 4; j++) Oacc[i][j] = 0ull;

    float mrow[4], lrow[4];
    #pragma unroll
    for (int i = 0; i < 4; i++) { mrow[i] = -1e30f; lrow[i] = 0.f; }

    const int kb0 = (m0 >= WIN) ? ((m0 - WIN) >> 6) : 0;
    const int kbm = m0 >> 6;

    for (int kb = kb0; kb <= kbm; kb++) {
        const int n0 = kb * BN;
        const bool need_mask = (n0 == m0) || (n0 + WIN == m0);

        __syncthreads();   // previous PV done reading P/V; safe to overwrite K/V
        // ---- load K (pair-transposed) and V tiles ----
        {
            const size_t kvbase = ((size_t)(bb * T_ + n0) * NKV + kh) * D_;
            #pragma unroll
            for (int i = 0; i < 8; i++) {
                int idx = tid + i * NTHREADS;
                int key = idx >> 5;
                int d4  = (idx & 31) << 2;
                size_t g = kvbase + (size_t)key * (NKV * D_) + d4;
                float4 k4 = *(const float4*)(K + g);
                float4 v4 = *(const float4*)(V + g);
                int p0 = d4 >> 1;                              // k-pair row
                ((float2*)ks)[p0 * 66 + key]       = make_float2(k4.x, k4.y);
                ((float2*)ks)[(p0 + 1) * 66 + key] = make_float2(k4.z, k4.w);
                *(float4*)(vs + key * D_ + d4) = v4;
            }
        }
        __syncthreads();

        // ---- S = Q K^T (64x64); accumulate f32x2 pairs along k ----
        u64 acc[4][4];
        #pragma unroll
        for (int i = 0; i < 4; i++)
            #pragma unroll
            for (int j = 0; j < 4; j++) acc[i][j] = 0ull;

        const float2* kp = (const float2*)ks;
        #pragma unroll 4
        for (int p2 = 0; p2 < 32; p2++) {                      // 4 k-values per iter
            ulonglong2 qv[4];
            #pragma unroll
            for (int i = 0; i < 4; i++)
                qv[i] = *(const ulonglong2*)(qs + (r0 + i) * D_ + p2 * 4);
            ulonglong2 ka = *(const ulonglong2*)(kp + (2*p2)   * 66 + c0);
            ulonglong2 kb2= *(const ulonglong2*)(kp + (2*p2)   * 66 + c0 + 2);
            ulonglong2 kc = *(const ulonglong2*)(kp + (2*p2+1) * 66 + c0);
            ulonglong2 kd = *(const ulonglong2*)(kp + (2*p2+1) * 66 + c0 + 2);
            #pragma unroll
            for (int i = 0; i < 4; i++) {
                ffma2(acc[i][0], qv[i].x, ka.x);
                ffma2(acc[i][1], qv[i].x, ka.y);
                ffma2(acc[i][2], qv[i].x, kb2.x);
                ffma2(acc[i][3], qv[i].x, kb2.y);
                ffma2(acc[i][0], qv[i].y, kc.x);
                ffma2(acc[i][1], qv[i].y, kc.y);
                ffma2(acc[i][2], qv[i].y, kd.x);
                ffma2(acc[i][3], qv[i].y, kd.y);
            }
        }

        float S[4][4];
        #pragma unroll
        for (int i = 0; i < 4; i++)
            #pragma unroll
            for (int j = 0; j < 4; j++) {
                float2 f = unpack2(acc[i][j]);
                S[i][j] = f.x + f.y;
            }

        if (need_mask) {
            #pragma unroll
            for (int i = 0; i < 4; i++) {
                int qpos = m0 + r0 + i;
                #pragma unroll
                for (int j = 0; j < 4; j++) {
                    int kpos = n0 + c0 + j;
                    if (kpos > qpos || kpos + WIN <= qpos) S[i][j] = -1e30f;
                }
            }
        }

        // ---- online softmax update ----
        float scale[4], P[4][4];
        #pragma unroll
        for (int i = 0; i < 4; i++) {
            float mx = fmaxf(fmaxf(S[i][0], S[i][1]), fmaxf(S[i][2], S[i][3]));
            #pragma unroll
            for (int o = 8; o; o >>= 1)
                mx = fmaxf(mx, __shfl_xor_sync(0xffffffffu, mx, o));
            float mnew = fmaxf(mrow[i], mx);
            scale[i] = __expf(mrow[i] - mnew);
            mrow[i] = mnew;
            float s = 0.f;
            #pragma unroll
            for (int j = 0; j < 4; j++) { P[i][j] = __expf(S[i][j] - mnew); s += P[i][j]; }
            #pragma unroll
            for (int o = 8; o; o >>= 1)
                s += __shfl_xor_sync(0xffffffffu, s, o);
            lrow[i] = lrow[i] * scale[i] + s;
        }
        #pragma unroll
        for (int i = 0; i < 4; i++) {
            u64 sc = pack2(scale[i], scale[i]);
            #pragma unroll
            for (int j = 0; j < 4; j++) fmul2(Oacc[i][j], sc);
        }

        __syncthreads();   // all warps done reading ks (P aliases it)
        #pragma unroll
        for (int i = 0; i < 4; i++)
            *(float4*)(ps + (r0 + i) * 76 + c0) =
                make_float4(P[i][0], P[i][1], P[i][2], P[i][3]);
        __syncthreads();

        // ---- O += P V (64x64 x 64x128); f32x2 pairs along output cols ----
        #pragma unroll 2
        for (int s2 = 0; s2 < 32; s2++) {                      // 2 keys per iter
            float2 pv[4];
            #pragma unroll
            for (int i = 0; i < 4; i++)
                pv[i] = *(const float2*)(ps + (r0 + i) * 76 + 2 * s2);
            ulonglong2 va = *(const ulonglong2*)(vs + (2*s2)   * D_ + c0v);
            ulonglong2 vb = *(const ulonglong2*)(vs + (2*s2)   * D_ + c0v + 4);
            ulonglong2 vc = *(const ulonglong2*)(vs + (2*s2+1) * D_ + c0v);
            ulonglong2 vd = *(const ulonglong2*)(vs + (2*s2+1) * D_ + c0v + 4);
            #pragma unroll
            for (int i = 0; i < 4; i++) {
                u64 pa = pack2(pv[i].x, pv[i].x);
                u64 pb = pack2(pv[i].y, pv[i].y);
                ffma2(Oacc[i][0], pa, va.x);
                ffma2(Oacc[i][1], pa, va.y);
                ffma2(Oacc[i][2], pa, vb.x);
                ffma2(Oacc[i][3], pa, vb.y);
                ffma2(Oacc[i][0], pb, vc.x);
                ffma2(Oacc[i][1], pb, vc.y);
                ffma2(Oacc[i][2], pb, vd.x);
                ffma2(Oacc[i][3], pb, vd.y);
            }
        }
    }

    // ---- epilogue: normalize and store ----
    #pragma unroll
    for (int i = 0; i < 4; i++) {
        float inv = 1.0f / lrow[i];
        size_t ob = ((size_t)(bb * T_ + m0 + r0 + i) * NH + h) * D_ + c0v;
        float2 a = unpack2(Oacc[i][0]);
        float2 b = unpack2(Oacc[i][1]);
        float2 c = unpack2(Oacc[i][2]);
        float2 d = unpack2(Oacc[i][3]);
        *(float4*)(Out + ob)     = make_float4(a.x*inv, a.y*inv, b.x*inv, b.y*inv);
        *(float4*)(Out + ob + 4) = make_float4(c.x*inv, c.y*inv, d.x*inv, d.y*inv);
    }
}

extern "C" void kernel_launch(void* const* d_in, const int* in_sizes, int n_in,
                              void* d_out, int out_size) {
    (void)in_sizes; (void)n_in; (void)out_size;
    const float* Q = (const float*)d_in[0];
    const float* K = (const float*)d_in[1];
    const float* V = (const float*)d_in[2];
    float* O = (float*)d_out;

    // not a stream op; safe under graph capture, idempotent
    cudaFuncSetAttribute(swa_fp32_kernel,
                         cudaFuncAttributeMaxDynamicSharedMemorySize,
                         SMEM_FLOATS * (int)sizeof(float));

    dim3 grid(T_ / BM, NH, B_);   // 64 x 16 x 4 = 4096 CTAs
    swa_fp32_kernel<<<grid, NTHREADS, SMEM_FLOATS * sizeof(float)>>>(Q, K, V, O);
}

// round 5
// speedup vs baseline: 1.5554x; 1.5554x over previous
#include <cuda_runtime.h>
#include <cuda_bf16.h>
#include <cstdint>

#define B_  4
#define T_  4096
#define NH  16
#define NKV 8
#define D_  128
#define WIN 1024
#define BM  64
#define BN  64
#define NTHREADS 256

#define QPAD 132   // padded row stride (floats) for Q/K/V smem tiles
#define PPAD 76    // P tile row stride

// shared memory layout (float offsets)
#define QS_OFF 0                        // Q: 64 x 132 = 8448
#define VS_OFF 8448                     // V: 64 x 132 = 8448
#define KS_OFF 16896                    // K: 64 x 132 = 8448
#define PS_OFF 16896                    // P (64 x 76 = 4864) aliases K buffer
#define SMEM_FLOATS (16896 + 8448)      // 25344 floats = 99 KB -> 2 CTAs/SM

typedef unsigned long long u64;

__device__ __forceinline__ void ffma2(u64 &d, u64 a, u64 b) {
    asm("fma.rn.f32x2 %0, %1, %2, %0;" : "+l"(d) : "l"(a), "l"(b));
}
__device__ __forceinline__ void fmul2(u64 &d, u64 s) {
    asm("mul.rn.f32x2 %0, %0, %1;" : "+l"(d) : "l"(s));
}
__device__ __forceinline__ u64 pack2(float x, float y) {
    u64 u; asm("mov.b64 %0, {%1, %2};" : "=l"(u) : "f"(x), "f"(y)); return u;
}
__device__ __forceinline__ float2 unpack2(u64 u) {
    float2 f; asm("mov.b64 {%0, %1}, %2;" : "=f"(f.x), "=f"(f.y) : "l"(u)); return f;
}

__global__ void __launch_bounds__(NTHREADS, 2)
swa_fp32_kernel(const float* __restrict__ Q, const float* __restrict__ K,
                const float* __restrict__ V, float* __restrict__ Out)
{
    extern __shared__ float smem[];
    float* qs = smem + QS_OFF;
    float* vs = smem + VS_OFF;
    float* ks = smem + KS_OFF;
    float* ps = smem + PS_OFF;

    const int tid = threadIdx.x;
    const int tx  = tid & 15;
    const int ty  = tid >> 4;
    const int m0  = blockIdx.x * BM;   // q-block start
    const int h   = blockIdx.y;        // q head
    const int bb  = blockIdx.z;        // batch
    const int kh  = h >> 1;            // GQA: 2 q heads per kv head

    const int r0  = ty * 4;            // my 4 S/O rows

    // ---- load Q tile (64 x 128 -> smem rows padded to 132) ----
    {
        const size_t qbase = ((size_t)(bb * T_ + m0) * NH + h) * D_;
        #pragma unroll
        for (int i = 0; i < 8; i++) {
            int idx = tid + i * NTHREADS;            // 2048 float4s
            int row = idx >> 5;
            int c4  = (idx & 31) << 2;
            float4 v4 = *(const float4*)(Q + qbase + (size_t)row * (NH * D_) + c4);
            *(float4*)(qs + row * QPAD + c4) = v4;
        }
    }

    // output accumulators: 4 rows x 4 f32x2.
    // j=0,1 -> output cols [4tx, 4tx+4); j=2,3 -> cols [64+4tx, 64+4tx+4)
    u64 Oacc[4][4];
    #pragma unroll
    for (int i = 0; i < 4; i++)
        #pragma unroll
        for (int j = 0; j < 4; j++) Oacc[i][j] = 0ull;

    float mrow[4], lrow[4];
    #pragma unroll
    for (int i = 0; i < 4; i++) { mrow[i] = -1e30f; lrow[i] = 0.f; }

    const int kb0 = (m0 >= WIN) ? ((m0 - WIN) >> 6) : 0;
    const int kbm = m0 >> 6;

    for (int kb = kb0; kb <= kbm; kb++) {
        const int n0 = kb * BN;
        const bool need_mask = (n0 == m0) || (n0 + WIN == m0);

        __syncthreads();   // previous PV done reading P/V; safe to overwrite K/V
        // ---- load K and V tiles (natural layout, padded rows) ----
        {
            const size_t kvbase = ((size_t)(bb * T_ + n0) * NKV + kh) * D_;
            #pragma unroll
            for (int i = 0; i < 8; i++) {
                int idx = tid + i * NTHREADS;
                int key = idx >> 5;
                int d4  = (idx & 31) << 2;
                size_t g = kvbase + (size_t)key * (NKV * D_) + d4;
                float4 k4 = *(const float4*)(K + g);
                float4 v4 = *(const float4*)(V + g);
                *(float4*)(ks + key * QPAD + d4) = k4;
                *(float4*)(vs + key * QPAD + d4) = v4;
            }
        }
        __syncthreads();

        // ---- S = Q K^T (64x64); f32x2 pairs run ALONG k ----
        // thread keys: tx + 16j  (j = 0..3)
        u64 acc[4][4];
        #pragma unroll
        for (int i = 0; i < 4; i++)
            #pragma unroll
            for (int j = 0; j < 4; j++) acc[i][j] = 0ull;

        #pragma unroll 4
        for (int p2 = 0; p2 < 32; p2++) {                      // 4 k-values per iter
            ulonglong2 qv[4], kv[4];
            #pragma unroll
            for (int i = 0; i < 4; i++)
                qv[i] = *(const ulonglong2*)(qs + (r0 + i) * QPAD + p2 * 4);
            #pragma unroll
            for (int j = 0; j < 4; j++)
                kv[j] = *(const ulonglong2*)(ks + (tx + 16 * j) * QPAD + p2 * 4);
            #pragma unroll
            for (int i = 0; i < 4; i++) {
                #pragma unroll
                for (int j = 0; j < 4; j++) {
                    ffma2(acc[i][j], qv[i].x, kv[j].x);
                    ffma2(acc[i][j], qv[i].y, kv[j].y);
                }
            }
        }

        float S[4][4];
        #pragma unroll
        for (int i = 0; i < 4; i++)
            #pragma unroll
            for (int j = 0; j < 4; j++) {
                float2 f = unpack2(acc[i][j]);
                S[i][j] = f.x + f.y;
            }

        if (need_mask) {
            #pragma unroll
            for (int i = 0; i < 4; i++) {
                int qpos = m0 + r0 + i;
                #pragma unroll
                for (int j = 0; j < 4; j++) {
                    int kpos = n0 + tx + 16 * j;
                    if (kpos > qpos || kpos + WIN <= qpos) S[i][j] = -1e30f;
                }
            }
        }

        // ---- online softmax update (reduce across the 16 tx lanes) ----
        float scale[4], P[4][4];
        #pragma unroll
        for (int i = 0; i < 4; i++) {
            float mx = fmaxf(fmaxf(S[i][0], S[i][1]), fmaxf(S[i][2], S[i][3]));
            #pragma unroll
            for (int o = 8; o; o >>= 1)
                mx = fmaxf(mx, __shfl_xor_sync(0xffffffffu, mx, o));
            float mnew = fmaxf(mrow[i], mx);
            scale[i] = __expf(mrow[i] - mnew);
            mrow[i] = mnew;
            float s = 0.f;
            #pragma unroll
            for (int j = 0; j < 4; j++) { P[i][j] = __expf(S[i][j] - mnew); s += P[i][j]; }
            #pragma unroll
            for (int o = 8; o; o >>= 1)
                s += __shfl_xor_sync(0xffffffffu, s, o);
            lrow[i] = lrow[i] * scale[i] + s;
        }
        #pragma unroll
        for (int i = 0; i < 4; i++) {
            u64 sc = pack2(scale[i], scale[i]);
            #pragma unroll
            for (int j = 0; j < 4; j++) fmul2(Oacc[i][j], sc);
        }

        __syncthreads();   // all warps done reading ks (P aliases it)
        #pragma unroll
        for (int i = 0; i < 4; i++)
            #pragma unroll
            for (int j = 0; j < 4; j++)
                ps[(r0 + i) * PPAD + tx + 16 * j] = P[i][j];
        __syncthreads();

        // ---- O += P V ; f32x2 pairs along output cols ----
        #pragma unroll 2
        for (int s2 = 0; s2 < 32; s2++) {                      // 2 keys per iter
            float2 pv[4];
            #pragma unroll
            for (int i = 0; i < 4; i++)
                pv[i] = *(const float2*)(ps + (r0 + i) * PPAD + 2 * s2);
            ulonglong2 va = *(const ulonglong2*)(vs + (2*s2)   * QPAD + 4 * tx);
            ulonglong2 vb = *(const ulonglong2*)(vs + (2*s2)   * QPAD + 4 * tx + 64);
            ulonglong2 vc = *(const ulonglong2*)(vs + (2*s2+1) * QPAD + 4 * tx);
            ulonglong2 vd = *(const ulonglong2*)(vs + (2*s2+1) * QPAD + 4 * tx + 64);
            #pragma unroll
            for (int i = 0; i < 4; i++) {
                u64 pa = pack2(pv[i].x, pv[i].x);
                u64 pb = pack2(pv[i].y, pv[i].y);
                ffma2(Oacc[i][0], pa, va.x);
                ffma2(Oacc[i][1], pa, va.y);
                ffma2(Oacc[i][2], pa, vb.x);
                ffma2(Oacc[i][3], pa, vb.y);
                ffma2(Oacc[i][0], pb, vc.x);
                ffma2(Oacc[i][1], pb, vc.y);
                ffma2(Oacc[i][2], pb, vd.x);
                ffma2(Oacc[i][3], pb, vd.y);
            }
        }
    }

    // ---- epilogue: normalize and store ----
    #pragma unroll
    for (int i = 0; i < 4; i++) {
        float inv = 1.0f / lrow[i];
        size_t ob = ((size_t)(bb * T_ + m0 + r0 + i) * NH + h) * D_;
        float2 a = unpack2(Oacc[i][0]);
        float2 b = unpack2(Oacc[i][1]);
        float2 c = unpack2(Oacc[i][2]);
        float2 d = unpack2(Oacc[i][3]);
        *(float4*)(Out + ob + 4 * tx) =
            make_float4(a.x*inv, a.y*inv, b.x*inv, b.y*inv);
        *(float4*)(Out + ob + 64 + 4 * tx) =
            make_float4(c.x*inv, c.y*inv, d.x*inv, d.y*inv);
    }
}

extern "C" void kernel_launch(void* const* d_in, const int* in_sizes, int n_in,
                              void* d_out, int out_size) {
    (void)in_sizes; (void)n_in; (void)out_size;
    const float* Q = (const float*)d_in[0];
    const float* K = (const float*)d_in[1];
    const float* V = (const float*)d_in[2];
    float* O = (float*)d_out;

    cudaFuncSetAttribute(swa_fp32_kernel,
                         cudaFuncAttributeMaxDynamicSharedMemorySize,
                         SMEM_FLOATS * (int)sizeof(float));

    dim3 grid(T_ / BM, NH, B_);   // 64 x 16 x 4 = 4096 CTAs
    swa_fp32_kernel<<<grid, NTHREADS, SMEM_FLOATS * sizeof(float)>>>(Q, K, V, O);
}

// round 6
// speedup vs baseline: 1.5562x; 1.0005x over previous
#include <cuda_runtime.h>
#include <cuda_bf16.h>
#include <cstdint>

#define B_  4
#define T_  4096
#define NH  16
#define NKV 8
#define D_  128
#define WIN 1024
#define BM  64
#define BN  64
#define NTHREADS 256

#define QPAD 132   // padded row stride (floats) for Q/K/V smem tiles
#define PPAD 76    // P tile row stride

// shared memory layout (float offsets)
#define QS_OFF 0                        // Q: 64 x 132 = 8448
#define VS_OFF 8448                     // V: 64 x 132 = 8448
#define KS_OFF 16896                    // K: 64 x 132 = 8448
#define PS_OFF 16896                    // P (64 x 76 = 4864) aliases K buffer
#define SMEM_FLOATS (16896 + 8448)      // 25344 floats = 99 KB -> 2 CTAs/SM

typedef unsigned long long u64;

__device__ __forceinline__ void ffma2(u64 &d, u64 a, u64 b) {
    asm("fma.rn.f32x2 %0, %1, %2, %0;" : "+l"(d) : "l"(a), "l"(b));
}
__device__ __forceinline__ void fmul2(u64 &d, u64 s) {
    asm("mul.rn.f32x2 %0, %0, %1;" : "+l"(d) : "l"(s));
}
__device__ __forceinline__ u64 pack2(float x, float y) {
    u64 u; asm("mov.b64 %0, {%1, %2};" : "=l"(u) : "f"(x), "f"(y)); return u;
}
__device__ __forceinline__ float2 unpack2(u64 u) {
    float2 f; asm("mov.b64 {%0, %1}, %2;" : "=f"(f.x), "=f"(f.y) : "l"(u)); return f;
}

__global__ void __launch_bounds__(NTHREADS, 2)
swa_fp32_kernel(const float* __restrict__ Q, const float* __restrict__ K,
                const float* __restrict__ V, float* __restrict__ Out)
{
    extern __shared__ float smem[];
    float* qs = smem + QS_OFF;
    float* vs = smem + VS_OFF;
    float* ks = smem + KS_OFF;
    float* ps = smem + PS_OFF;

    const int tid = threadIdx.x;
    const int tx  = tid & 15;
    const int ty  = tid >> 4;
    const int m0  = blockIdx.x * BM;   // q-block start
    const int h   = blockIdx.y;        // q head
    const int bb  = blockIdx.z;        // batch
    const int kh  = h >> 1;            // GQA: 2 q heads per kv head

    const int r0  = ty * 4;            // my 4 S/O rows

    // ---- load Q tile (64 x 128 -> smem rows padded to 132) ----
    {
        const size_t qbase = ((size_t)(bb * T_ + m0) * NH + h) * D_;
        #pragma unroll
        for (int i = 0; i < 8; i++) {
            int idx = tid + i * NTHREADS;            // 2048 float4s
            int row = idx >> 5;
            int c4  = (idx & 31) << 2;
            float4 v4 = *(const float4*)(Q + qbase + (size_t)row * (NH * D_) + c4);
            *(float4*)(qs + row * QPAD + c4) = v4;
        }
    }

    // output accumulators: 4 rows x 4 f32x2.
    // j=0,1 -> output cols [4tx, 4tx+4); j=2,3 -> cols [64+4tx, 64+4tx+4)
    u64 Oacc[4][4];
    #pragma unroll
    for (int i = 0; i < 4; i++)
        #pragma unroll
        for (int j = 0; j < 4; j++) Oacc[i][j] = 0ull;

    float mrow[4], lrow[4];
    #pragma unroll
    for (int i = 0; i < 4; i++) { mrow[i] = -1e30f; lrow[i] = 0.f; }

    const int kb0 = (m0 >= WIN) ? ((m0 - WIN) >> 6) : 0;
    const int kbm = m0 >> 6;

    for (int kb = kb0; kb <= kbm; kb++) {
        const int n0 = kb * BN;
        const bool need_mask = (n0 == m0) || (n0 + WIN == m0);

        __syncthreads();   // previous PV done reading P/V; safe to overwrite K/V
        // ---- load K and V tiles (natural layout, padded rows) ----
        {
            const size_t kvbase = ((size_t)(bb * T_ + n0) * NKV + kh) * D_;
            #pragma unroll
            for (int i = 0; i < 8; i++) {
                int idx = tid + i * NTHREADS;
                int key = idx >> 5;
                int d4  = (idx & 31) << 2;
                size_t g = kvbase + (size_t)key * (NKV * D_) + d4;
                float4 k4 = *(const float4*)(K + g);
                float4 v4 = *(const float4*)(V + g);
                *(float4*)(ks + key * QPAD + d4) = k4;
                *(float4*)(vs + key * QPAD + d4) = v4;
            }
        }
        __syncthreads();

        // ---- S = Q K^T (64x64); f32x2 pairs run ALONG k ----
        // thread keys: tx + 16j  (j = 0..3)
        u64 acc[4][4];
        #pragma unroll
        for (int i = 0; i < 4; i++)
            #pragma unroll
            for (int j = 0; j < 4; j++) acc[i][j] = 0ull;

        #pragma unroll 4
        for (int p2 = 0; p2 < 32; p2++) {                      // 4 k-values per iter
            ulonglong2 qv[4], kv[4];
            #pragma unroll
            for (int i = 0; i < 4; i++)
                qv[i] = *(const ulonglong2*)(qs + (r0 + i) * QPAD + p2 * 4);
            #pragma unroll
            for (int j = 0; j < 4; j++)
                kv[j] = *(const ulonglong2*)(ks + (tx + 16 * j) * QPAD + p2 * 4);
            #pragma unroll
            for (int i = 0; i < 4; i++) {
                #pragma unroll
                for (int j = 0; j < 4; j++) {
                    ffma2(acc[i][j], qv[i].x, kv[j].x);
                    ffma2(acc[i][j], qv[i].y, kv[j].y);
                }
            }
        }

        float S[4][4];
        #pragma unroll
        for (int i = 0; i < 4; i++)
            #pragma unroll
            for (int j = 0; j < 4; j++) {
                float2 f = unpack2(acc[i][j]);
                S[i][j] = f.x + f.y;
            }

        if (need_mask) {
            #pragma unroll
            for (int i = 0; i < 4; i++) {
                int qpos = m0 + r0 + i;
                #pragma unroll
                for (int j = 0; j < 4; j++) {
                    int kpos = n0 + tx + 16 * j;
                    if (kpos > qpos || kpos + WIN <= qpos) S[i][j] = -1e30f;
                }
            }
        }

        // ---- online softmax update (reduce across the 16 tx lanes) ----
        float scale[4], P[4][4];
        #pragma unroll
        for (int i = 0; i < 4; i++) {
            float mx = fmaxf(fmaxf(S[i][0], S[i][1]), fmaxf(S[i][2], S[i][3]));
            #pragma unroll
            for (int o = 8; o; o >>= 1)
                mx = fmaxf(mx, __shfl_xor_sync(0xffffffffu, mx, o));
            float mnew = fmaxf(mrow[i], mx);
            scale[i] = __expf(mrow[i] - mnew);
            mrow[i] = mnew;
            float s = 0.f;
            #pragma unroll
            for (int j = 0; j < 4; j++) { P[i][j] = __expf(S[i][j] - mnew); s += P[i][j]; }
            #pragma unroll
            for (int o = 8; o; o >>= 1)
                s += __shfl_xor_sync(0xffffffffu, s, o);
            lrow[i] = lrow[i] * scale[i] + s;
        }
        #pragma unroll
        for (int i = 0; i < 4; i++) {
            u64 sc = pack2(scale[i], scale[i]);
            #pragma unroll
            for (int j = 0; j < 4; j++) fmul2(Oacc[i][j], sc);
        }

        __syncthreads();   // all warps done reading ks (P aliases it)
        #pragma unroll
        for (int i = 0; i < 4; i++)
            #pragma unroll
            for (int j = 0; j < 4; j++)
                ps[(r0 + i) * PPAD + tx + 16 * j] = P[i][j];
        __syncthreads();

        // ---- O += P V ; f32x2 pairs along output cols ----
        #pragma unroll 2
        for (int s2 = 0; s2 < 32; s2++) {                      // 2 keys per iter
            float2 pv[4];
            #pragma unroll
            for (int i = 0; i < 4; i++)
                pv[i] = *(const float2*)(ps + (r0 + i) * PPAD + 2 * s2);
            ulonglong2 va = *(const ulonglong2*)(vs + (2*s2)   * QPAD + 4 * tx);
            ulonglong2 vb = *(const ulonglong2*)(vs + (2*s2)   * QPAD + 4 * tx + 64);
            ulonglong2 vc = *(const ulonglong2*)(vs + (2*s2+1) * QPAD + 4 * tx);
            ulonglong2 vd = *(const ulonglong2*)(vs + (2*s2+1) * QPAD + 4 * tx + 64);
            #pragma unroll
            for (int i = 0; i < 4; i++) {
                u64 pa = pack2(pv[i].x, pv[i].x);
                u64 pb = pack2(pv[i].y, pv[i].y);
                ffma2(Oacc[i][0], pa, va.x);
                ffma2(Oacc[i][1], pa, va.y);
                ffma2(Oacc[i][2], pa, vb.x);
                ffma2(Oacc[i][3], pa, vb.y);
                ffma2(Oacc[i][0], pb, vc.x);
                ffma2(Oacc[i][1], pb, vc.y);
                ffma2(Oacc[i][2], pb, vd.x);
                ffma2(Oacc[i][3], pb, vd.y);
            }
        }
    }

    // ---- epilogue: normalize and store ----
    #pragma unroll
    for (int i = 0; i < 4; i++) {
        float inv = 1.0f / lrow[i];
        size_t ob = ((size_t)(bb * T_ + m0 + r0 + i) * NH + h) * D_;
        float2 a = unpack2(Oacc[i][0]);
        float2 b = unpack2(Oacc[i][1]);
        float2 c = unpack2(Oacc[i][2]);
        float2 d = unpack2(Oacc[i][3]);
        *(float4*)(Out + ob + 4 * tx) =
            make_float4(a.x*inv, a.y*inv, b.x*inv, b.y*inv);
        *(float4*)(Out + ob + 64 + 4 * tx) =
            make_float4(c.x*inv, c.y*inv, d.x*inv, d.y*inv);
    }
}

extern "C" void kernel_launch(void* const* d_in, const int* in_sizes, int n_in,
                              void* d_out, int out_size) {
    (void)in_sizes; (void)n_in; (void)out_size;
    const float* Q = (const float*)d_in[0];
    const float* K = (const float*)d_in[1];
    const float* V = (const float*)d_in[2];
    float* O = (float*)d_out;

    cudaFuncSetAttribute(swa_fp32_kernel,
                         cudaFuncAttributeMaxDynamicSharedMemorySize,
                         SMEM_FLOATS * (int)sizeof(float));

    dim3 grid(T_ / BM, NH, B_);   // 64 x 16 x 4 = 4096 CTAs
    swa_fp32_kernel<<<grid, NTHREADS, SMEM_FLOATS * sizeof(float)>>>(Q, K, V, O);
}

// round 8
// speedup vs baseline: 4.3143x; 2.7724x over previous
#include <cuda_runtime.h>
#include <cuda_bf16.h>
#include <cstdint>

#define B_   4
#define T_   4096
#define NH   16
#define NKV  8
#define D_   128
#define WIN  1024
#define BM   128
#define BN   64
#define NTHREADS 256

// bf16 tiles, rows padded to 136 elements = 272 bytes (272 mod 128 = 16 ->
// ldmatrix 8-row groups tile the 128B space exactly: conflict-free)
#define ROWB 272
#define QHI_OFF 0                       // 128 x 136 bf16 = 34816 B
#define QLO_OFF 34816
#define KHI_OFF 69632                   // 64 x 136 bf16 = 17408 B
#define KLO_OFF 87040
#define VHI_OFF 104448
#define VLO_OFF 121856
#define SMEM_BYTES 139264

__device__ __forceinline__ void ldsm_x4(uint32_t (&r)[4], uint32_t addr) {
    asm volatile("ldmatrix.sync.aligned.m8n8.x4.shared.b16 {%0,%1,%2,%3}, [%4];"
                 : "=r"(r[0]), "=r"(r[1]), "=r"(r[2]), "=r"(r[3]) : "r"(addr));
}
__device__ __forceinline__ void ldsm_x4_t(uint32_t (&r)[4], uint32_t addr) {
    asm volatile("ldmatrix.sync.aligned.m8n8.x4.trans.shared.b16 {%0,%1,%2,%3}, [%4];"
                 : "=r"(r[0]), "=r"(r[1]), "=r"(r[2]), "=r"(r[3]) : "r"(addr));
}
#define MMA(C, A, b0, b1) asm volatile( \
    "mma.sync.aligned.m16n8k16.row.col.f32.bf16.bf16.f32 " \
    "{%0,%1,%2,%3}, {%4,%5,%6,%7}, {%8,%9}, {%0,%1,%2,%3};" \
    : "+f"((C)[0]), "+f"((C)[1]), "+f"((C)[2]), "+f"((C)[3]) \
    : "r"((A)[0]), "r"((A)[1]), "r"((A)[2]), "r"((A)[3]), "r"(b0), "r"(b1))

__device__ __forceinline__ uint32_t bfu(__nv_bfloat162 v) {
    return *reinterpret_cast<uint32_t*>(&v);
}
// split a float pair into (hi, lo) packed bf16x2
__device__ __forceinline__ void split2(float x, float y, uint32_t &hi, uint32_t &lo) {
    __nv_bfloat162 h = __float22bfloat162_rn(make_float2(x, y));
    float2 g = __bfloat1622float2(h);
    __nv_bfloat162 l = __float22bfloat162_rn(make_float2(x - g.x, y - g.y));
    hi = bfu(h); lo = bfu(l);
}

__global__ void __launch_bounds__(NTHREADS, 1)
swa_mma_kernel(const float* __restrict__ Q, const float* __restrict__ K,
               const float* __restrict__ V, float* __restrict__ Out)
{
    extern __shared__ char smem[];
    uint32_t sbase;
    asm("{ .reg .u64 t; cvta.to.shared.u64 t, %1; cvt.u32.u64 %0, t; }"
        : "=r"(sbase) : "l"(smem));

    const int tid  = threadIdx.x;
    const int lane = tid & 31;
    const int wid  = tid >> 5;          // 8 warps, warp owns rows [16w, 16w+16)
    const int m0   = blockIdx.x * BM;
    const int h    = blockIdx.y;
    const int bb   = blockIdx.z;
    const int kh   = h >> 1;

    const int rb = wid * 16;
    const int tq = lane >> 2;           // 0..7
    const int tr = lane & 3;            // 0..3

    // ---- load + split Q tile (128 x 128) ----
    {
        const size_t qbase = ((size_t)(bb * T_ + m0) * NH + h) * D_;
        #pragma unroll
        for (int i = 0; i < 16; i++) {
            int idx = tid + i * NTHREADS;
            int row = idx >> 5, c4 = (idx & 31) << 2;
            float4 f = *(const float4*)(Q + qbase + (size_t)row * (NH * D_) + c4);
            uint32_t h0, l0, h1, l1;
            split2(f.x, f.y, h0, l0);
            split2(f.z, f.w, h1, l1);
            int off = row * ROWB + c4 * 2;
            *(uint2*)(smem + QHI_OFF + off) = make_uint2(h0, h1);
            *(uint2*)(smem + QLO_OFF + off) = make_uint2(l0, l1);
        }
    }

    // ldmatrix base addresses (lane-dependent parts precomputed)
    const uint32_t a_q_hi = sbase + QHI_OFF + (rb + (lane & 15)) * ROWB + ((lane >> 4) << 3) * 2;
    const uint32_t a_q_lo = a_q_hi + (QLO_OFF - QHI_OFF);
    const int k_row = ((lane >> 4) << 3) + (lane & 7);
    const int k_col = (((lane >> 3) & 1) << 3);
    const uint32_t a_k_hi = sbase + KHI_OFF + k_row * ROWB + k_col * 2;
    const uint32_t a_k_lo = a_k_hi + (KLO_OFF - KHI_OFF);
    const int v_row = (((lane >> 3) & 1) << 3) + (lane & 7);
    const int v_col = ((lane >> 4) << 3);
    const uint32_t a_v_hi = sbase + VHI_OFF + v_row * ROWB + v_col * 2;
    const uint32_t a_v_lo = a_v_hi + (VLO_OFF - VHI_OFF);

    // O accumulators: 16 d-tiles x 4 f32  (c0,c1 row R0; c2,c3 row R1)
    float O[16][4];
    #pragma unroll
    for (int j = 0; j < 16; j++)
        #pragma unroll
        for (int e = 0; e < 4; e++) O[j][e] = 0.f;

    float mr0 = -1e29f, mr1 = -1e29f, lr0 = 0.f, lr1 = 0.f;

    const int kb0 = (m0 >= WIN) ? ((m0 - WIN) >> 6) : 0;
    const int kbm = (m0 >> 6) + 1;

    for (int kb = kb0; kb <= kbm; kb++) {
        const int n0 = kb * BN;
        // mask needed if any causal violation (max key n0+BN-1 > min query m0)
        // or any window violation (min key n0 dead for max query m0+BM-1):
        const bool need_mask = (n0 >= m0) || (n0 + WIN < m0 + BM);

        __syncthreads();   // previous PV done reading V; safe to overwrite K/V
        // ---- load + split K, V tiles (64 x 128 each) ----
        {
            const size_t kvbase = ((size_t)(bb * T_ + n0) * NKV + kh) * D_;
            #pragma unroll
            for (int i = 0; i < 8; i++) {
                int idx = tid + i * NTHREADS;
                int key = idx >> 5, d4 = (idx & 31) << 2;
                size_t g = kvbase + (size_t)key * (NKV * D_) + d4;
                float4 fk = *(const float4*)(K + g);
                float4 fv = *(const float4*)(V + g);
                int off = key * ROWB + d4 * 2;
                uint32_t h0, l0, h1, l1;
                split2(fk.x, fk.y, h0, l0);
                split2(fk.z, fk.w, h1, l1);
                *(uint2*)(smem + KHI_OFF + off) = make_uint2(h0, h1);
                *(uint2*)(smem + KLO_OFF + off) = make_uint2(l0, l1);
                split2(fv.x, fv.y, h0, l0);
                split2(fv.z, fv.w, h1, l1);
                *(uint2*)(smem + VHI_OFF + off) = make_uint2(h0, h1);
                *(uint2*)(smem + VLO_OFF + off) = make_uint2(l0, l1);
            }
        }
        __syncthreads();

        // ---- S = Q K^T : 16 rows x 64 keys per warp, 3-MMA bf16 split ----
        float S[8][4];
        #pragma unroll
        for (int j = 0; j < 8; j++)
            #pragma unroll
            for (int e = 0; e < 4; e++) S[j][e] = 0.f;

        #pragma unroll
        for (int ks = 0; ks < 8; ks++) {            // k = 16*ks over d=128
            uint32_t ah[4], al[4];
            ldsm_x4(ah, a_q_hi + ks * 32);
            ldsm_x4(al, a_q_lo + ks * 32);
            #pragma unroll
            for (int np = 0; np < 4; np++) {        // key n-pairs (16 keys)
                uint32_t bh[4], bl[4];
                ldsm_x4(bh, a_k_hi + np * 16 * ROWB + ks * 32);
                ldsm_x4(bl, a_k_lo + np * 16 * ROWB + ks * 32);
                MMA(S[2*np],   ah, bh[0], bh[1]);
                MMA(S[2*np],   ah, bl[0], bl[1]);
                MMA(S[2*np],   al, bh[0], bh[1]);
                MMA(S[2*np+1], ah, bh[2], bh[3]);
                MMA(S[2*np+1], ah, bl[2], bl[3]);
                MMA(S[2*np+1], al, bh[2], bh[3]);
            }
        }

        if (need_mask) {
            const int q0 = m0 + rb + tq, q1 = q0 + 8;
            #pragma unroll
            for (int j = 0; j < 8; j++) {
                #pragma unroll
                for (int e = 0; e < 2; e++) {
                    int kp = n0 + 8 * j + 2 * tr + e;
                    if (kp > q0 || kp + WIN <= q0) S[j][e]     = -1e30f;
                    if (kp > q1 || kp + WIN <= q1) S[j][2 + e] = -1e30f;
                }
            }
        }

        // ---- online softmax (rows fully warp-private; quad reductions) ----
        float mx0 = -1e30f, mx1 = -1e30f;
        #pragma unroll
        for (int j = 0; j < 8; j++) {
            mx0 = fmaxf(mx0, fmaxf(S[j][0], S[j][1]));
            mx1 = fmaxf(mx1, fmaxf(S[j][2], S[j][3]));
        }
        mx0 = fmaxf(mx0, __shfl_xor_sync(0xffffffffu, mx0, 1));
        mx0 = fmaxf(mx0, __shfl_xor_sync(0xffffffffu, mx0, 2));
        mx1 = fmaxf(mx1, __shfl_xor_sync(0xffffffffu, mx1, 1));
        mx1 = fmaxf(mx1, __shfl_xor_sync(0xffffffffu, mx1, 2));
        const float mn0 = fmaxf(mr0, mx0), mn1 = fmaxf(mr1, mx1);
        const float sc0 = __expf(mr0 - mn0), sc1 = __expf(mr1 - mn1);
        mr0 = mn0; mr1 = mn1;

        float s0 = 0.f, s1 = 0.f;
        #pragma unroll
        for (int j = 0; j < 8; j++) {
            S[j][0] = __expf(S[j][0] - mn0); s0 += S[j][0];
            S[j][1] = __expf(S[j][1] - mn0); s0 += S[j][1];
            S[j][2] = __expf(S[j][2] - mn1); s1 += S[j][2];
            S[j][3] = __expf(S[j][3] - mn1); s1 += S[j][3];
        }
        s0 += __shfl_xor_sync(0xffffffffu, s0, 1);
        s0 += __shfl_xor_sync(0xffffffffu, s0, 2);
        s1 += __shfl_xor_sync(0xffffffffu, s1, 1);
        s1 += __shfl_xor_sync(0xffffffffu, s1, 2);
        lr0 = lr0 * sc0 + s0;
        lr1 = lr1 * sc1 + s1;

        #pragma unroll
        for (int j = 0; j < 16; j++) {
            O[j][0] *= sc0; O[j][1] *= sc0;
            O[j][2] *= sc1; O[j][3] *= sc1;
        }

        // ---- O += P V : P fragments repacked in registers from S ----
        #pragma unroll
        for (int j = 0; j < 4; j++) {               // key k-steps (16 keys)
            uint32_t ph[4], pl[4];
            split2(S[2*j][0],   S[2*j][1],   ph[0], pl[0]);
            split2(S[2*j][2],   S[2*j][3],   ph[1], pl[1]);
            split2(S[2*j+1][0], S[2*j+1][1], ph[2], pl[2]);
            split2(S[2*j+1][2], S[2*j+1][3], ph[3], pl[3]);
            #pragma unroll
            for (int dp = 0; dp < 8; dp++) {        // d n-pairs (16 cols)
                uint32_t bh[4], bl[4];
                ldsm_x4_t(bh, a_v_hi + j * 16 * ROWB + dp * 32);
                ldsm_x4_t(bl, a_v_lo + j * 16 * ROWB + dp * 32);
                MMA(O[2*dp],   ph, bh[0], bh[1]);
                MMA(O[2*dp],   ph, bl[0], bl[1]);
                MMA(O[2*dp],   pl, bh[0], bh[1]);
                MMA(O[2*dp+1], ph, bh[2], bh[3]);
                MMA(O[2*dp+1], ph, bl[2], bl[3]);
                MMA(O[2*dp+1], pl, bh[2], bh[3]);
            }
        }
    }

    // ---- epilogue: normalize and store ----
    const float inv0 = 1.0f / lr0, inv1 = 1.0f / lr1;
    const int r0g = m0 + rb + tq;
    const size_t ob0 = ((size_t)(bb * T_ + r0g) * NH + h) * D_;
    const size_t ob1 = ((size_t)(bb * T_ + r0g + 8) * NH + h) * D_;
    #pragma unroll
    for (int j = 0; j < 16; j++) {
        int col = 8 * j + 2 * tr;
        *(float2*)(Out + ob0 + col) = make_float2(O[j][0] * inv0, O[j][1] * inv0);
        *(float2*)(Out + ob1 + col) = make_float2(O[j][2] * inv1, O[j][3] * inv1);
    }
}

extern "C" void kernel_launch(void* const* d_in, const int* in_sizes, int n_in,
                              void* d_out, int out_size) {
    (void)in_sizes; (void)n_in; (void)out_size;
    const float* Q = (const float*)d_in[0];
    const float* K = (const float*)d_in[1];
    const float* V = (const float*)d_in[2];
    float* O = (float*)d_out;

    cudaFuncSetAttribute(swa_mma_kernel,
                         cudaFuncAttributeMaxDynamicSharedMemorySize, SMEM_BYTES);

    dim3 grid(T_ / BM, NH, B_);   // 32 x 16 x 4 = 2048 CTAs
    swa_mma_kernel<<<grid, NTHREADS, SMEM_BYTES>>>(Q, K, V, O);
}

// round 9
// speedup vs baseline: 4.8162x; 1.1163x over previous
#include <cuda_runtime.h>
#include <cuda_fp16.h>
#include <cstdint>

#define B_   4
#define T_   4096
#define NH   16
#define NKV  8
#define D_   128
#define WIN  1024
#define BM   128
#define BN   64
#define NTHREADS 256

// fp16 tiles, rows padded to 136 elements = 272 bytes (272 mod 128 = 16 ->
// ldmatrix 8-row groups tile the 128B space exactly: conflict-free)
#define ROWB 272
#define QHI_OFF 0                       // 128 x 136 f16 = 34816 B
#define QLO_OFF 34816
#define KHI_OFF 69632                   // 64 x 136 f16 = 17408 B
#define KLO_OFF 87040
#define VHI_OFF 104448
#define VLO_OFF 121856
#define STAGE_K 139264                  // 64 x 128 f32 staging = 32768 B
#define STAGE_V 172032
#define SMEM_BYTES 204800               // < 227 KB -> 1 CTA/SM

__device__ __forceinline__ void ldsm_x4(uint32_t (&r)[4], uint32_t addr) {
    asm volatile("ldmatrix.sync.aligned.m8n8.x4.shared.b16 {%0,%1,%2,%3}, [%4];"
                 : "=r"(r[0]), "=r"(r[1]), "=r"(r[2]), "=r"(r[3]) : "r"(addr));
}
__device__ __forceinline__ void ldsm_x4_t(uint32_t (&r)[4], uint32_t addr) {
    asm volatile("ldmatrix.sync.aligned.m8n8.x4.trans.shared.b16 {%0,%1,%2,%3}, [%4];"
                 : "=r"(r[0]), "=r"(r[1]), "=r"(r[2]), "=r"(r[3]) : "r"(addr));
}
#define MMA(C, A, b0, b1) asm volatile( \
    "mma.sync.aligned.m16n8k16.row.col.f32.f16.f16.f32 " \
    "{%0,%1,%2,%3}, {%4,%5,%6,%7}, {%8,%9}, {%0,%1,%2,%3};" \
    : "+f"((C)[0]), "+f"((C)[1]), "+f"((C)[2]), "+f"((C)[3]) \
    : "r"((A)[0]), "r"((A)[1]), "r"((A)[2]), "r"((A)[3]), "r"(b0), "r"(b1))

#define CPA16(dst, src) asm volatile( \
    "cp.async.cg.shared.global [%0], [%1], 16;" :: "r"(dst), "l"(src))
#define CPA_COMMIT asm volatile("cp.async.commit_group;")
#define CPA_WAIT0  asm volatile("cp.async.wait_group 0;")

__device__ __forceinline__ uint32_t hbits(__half2 v) {
    return *reinterpret_cast<uint32_t*>(&v);
}
__device__ __forceinline__ uint32_t packh2(float x, float y) {
    __half2 h = __floats2half2_rn(x, y);
    return hbits(h);
}
// split a float pair into (hi, lo) packed f16x2
__device__ __forceinline__ void split2h(float x, float y, uint32_t &hi, uint32_t &lo) {
    __half2 h = __floats2half2_rn(x, y);
    float2 g = __half22float2(h);
    __half2 l = __floats2half2_rn(x - g.x, y - g.y);
    hi = hbits(h); lo = hbits(l);
}

__global__ void __launch_bounds__(NTHREADS, 1)
swa_mma_kernel(const float* __restrict__ Q, const float* __restrict__ K,
               const float* __restrict__ V, float* __restrict__ Out)
{
    extern __shared__ char smem[];
    uint32_t sbase;
    asm("{ .reg .u64 t; cvta.to.shared.u64 t, %1; cvt.u32.u64 %0, t; }"
        : "=r"(sbase) : "l"(smem));

    const int tid  = threadIdx.x;
    const int lane = tid & 31;
    const int wid  = tid >> 5;          // 8 warps, warp owns rows [16w, 16w+16)
    const int m0   = blockIdx.x * BM;
    const int h    = blockIdx.y;
    const int bb   = blockIdx.z;
    const int kh   = h >> 1;

    const int rb = wid * 16;
    const int tq = lane >> 2;           // 0..7
    const int tr = lane & 3;            // 0..3

    const int kb0 = (m0 >= WIN) ? ((m0 - WIN) >> 6) : 0;
    const int kbm = (m0 >> 6) + 1;

    // per-thread staging indices (fixed for all tiles)
    const int ld_key = tid >> 5;                 // rows: 8 per pass
    const int ld_d4  = (tid & 31) << 2;          // 16B column chunk
    const size_t kvhead = (size_t)(bb * T_) * (NKV * D_) + (size_t)kh * D_;

    // ---- prefetch first K/V tile into fp32 staging via cp.async ----
    {
        const size_t kvb = kvhead + (size_t)kb0 * BN * (NKV * D_);
        #pragma unroll
        for (int i = 0; i < 8; i++) {
            int key = ld_key + i * 8;
            uint32_t so = (uint32_t)(key * D_ + ld_d4) * 4;
            const size_t g = kvb + (size_t)key * (NKV * D_) + ld_d4;
            CPA16(sbase + STAGE_K + so, K + g);
            CPA16(sbase + STAGE_V + so, V + g);
        }
        CPA_COMMIT;
    }

    // ---- load + split Q tile (128 x 128) while prefetch flies ----
    {
        const size_t qbase = ((size_t)(bb * T_ + m0) * NH + h) * D_;
        #pragma unroll
        for (int i = 0; i < 16; i++) {
            int idx = tid + i * NTHREADS;
            int row = idx >> 5, c4 = (idx & 31) << 2;
            float4 f = *(const float4*)(Q + qbase + (size_t)row * (NH * D_) + c4);
            uint32_t h0, l0, h1, l1;
            split2h(f.x, f.y, h0, l0);
            split2h(f.z, f.w, h1, l1);
            int off = row * ROWB + c4 * 2;
            *(uint2*)(smem + QHI_OFF + off) = make_uint2(h0, h1);
            *(uint2*)(smem + QLO_OFF + off) = make_uint2(l0, l1);
        }
    }

    // ldmatrix base addresses (lane-dependent parts precomputed)
    const uint32_t a_q_hi = sbase + QHI_OFF + (rb + (lane & 15)) * ROWB + ((lane >> 4) << 3) * 2;
    const uint32_t a_q_lo = a_q_hi + (QLO_OFF - QHI_OFF);
    const int k_row = ((lane >> 4) << 3) + (lane & 7);
    const int k_col = (((lane >> 3) & 1) << 3);
    const uint32_t a_k_hi = sbase + KHI_OFF + k_row * ROWB + k_col * 2;
    const uint32_t a_k_lo = a_k_hi + (KLO_OFF - KHI_OFF);
    const int v_row = (((lane >> 3) & 1) << 3) + (lane & 7);
    const int v_col = ((lane >> 4) << 3);
    const uint32_t a_v_hi = sbase + VHI_OFF + v_row * ROWB + v_col * 2;
    const uint32_t a_v_lo = a_v_hi + (VLO_OFF - VHI_OFF);

    // O accumulators: 16 d-tiles x 4 f32  (c0,c1 row R0; c2,c3 row R1)
    float O[16][4];
    #pragma unroll
    for (int j = 0; j < 16; j++)
        #pragma unroll
        for (int e = 0; e < 4; e++) O[j][e] = 0.f;

    float mr0 = -1e29f, mr1 = -1e29f, lr0 = 0.f, lr1 = 0.f;

    for (int kb = kb0; kb <= kbm; kb++) {
        const int n0 = kb * BN;
        // mask needed if any causal violation (max key n0+BN-1 > min query m0)
        // or any window violation (min key n0 dead for max query m0+BM-1):
        const bool need_mask = (n0 >= m0) || (n0 + WIN < m0 + BM);

        // staging for tile kb has landed; previous tile's GEMMs are done
        CPA_WAIT0;
        __syncthreads();

        // ---- split staged fp32 K/V -> f16 hi/lo tiles ----
        #pragma unroll
        for (int i = 0; i < 8; i++) {
            int key = ld_key + i * 8;
            uint32_t so = (uint32_t)(key * D_ + ld_d4) * 4;
            float4 fk = *(const float4*)(smem + STAGE_K + so);
            float4 fv = *(const float4*)(smem + STAGE_V + so);
            int off = key * ROWB + ld_d4 * 2;
            uint32_t h0, l0, h1, l1;
            split2h(fk.x, fk.y, h0, l0);
            split2h(fk.z, fk.w, h1, l1);
            *(uint2*)(smem + KHI_OFF + off) = make_uint2(h0, h1);
            *(uint2*)(smem + KLO_OFF + off) = make_uint2(l0, l1);
            split2h(fv.x, fv.y, h0, l0);
            split2h(fv.z, fv.w, h1, l1);
            *(uint2*)(smem + VHI_OFF + off) = make_uint2(h0, h1);
            *(uint2*)(smem + VLO_OFF + off) = make_uint2(l0, l1);
        }
        __syncthreads();   // staging consumed; hi/lo tiles published

        // ---- prefetch next tile (overlaps with GEMM phase) ----
        if (kb < kbm) {
            const size_t kvb = kvhead + (size_t)(n0 + BN) * (NKV * D_);
            #pragma unroll
            for (int i = 0; i < 8; i++) {
                int key = ld_key + i * 8;
                uint32_t so = (uint32_t)(key * D_ + ld_d4) * 4;
                const size_t g = kvb + (size_t)key * (NKV * D_) + ld_d4;
                CPA16(sbase + STAGE_K + so, K + g);
                CPA16(sbase + STAGE_V + so, V + g);
            }
            CPA_COMMIT;
        }

        // ---- S = Q K^T : 16 rows x 64 keys per warp, 3-MMA f16 split ----
        float S[8][4];
        #pragma unroll
        for (int j = 0; j < 8; j++)
            #pragma unroll
            for (int e = 0; e < 4; e++) S[j][e] = 0.f;

        #pragma unroll
        for (int ks = 0; ks < 8; ks++) {            // k = 16*ks over d=128
            uint32_t ah[4], al[4];
            ldsm_x4(ah, a_q_hi + ks * 32);
            ldsm_x4(al, a_q_lo + ks * 32);
            #pragma unroll
            for (int np = 0; np < 4; np++) {        // key n-pairs (16 keys)
                uint32_t bh[4], bl[4];
                ldsm_x4(bh, a_k_hi + np * 16 * ROWB + ks * 32);
                ldsm_x4(bl, a_k_lo + np * 16 * ROWB + ks * 32);
                MMA(S[2*np],   ah, bh[0], bh[1]);
                MMA(S[2*np],   ah, bl[0], bl[1]);
                MMA(S[2*np],   al, bh[0], bh[1]);
                MMA(S[2*np+1], ah, bh[2], bh[3]);
                MMA(S[2*np+1], ah, bl[2], bl[3]);
                MMA(S[2*np+1], al, bh[2], bh[3]);
            }
        }

        if (need_mask) {
            const int q0 = m0 + rb + tq, q1 = q0 + 8;
            #pragma unroll
            for (int j = 0; j < 8; j++) {
                #pragma unroll
                for (int e = 0; e < 2; e++) {
                    int kp = n0 + 8 * j + 2 * tr + e;
                    if (kp > q0 || kp + WIN <= q0) S[j][e]     = -1e30f;
                    if (kp > q1 || kp + WIN <= q1) S[j][2 + e] = -1e30f;
                }
            }
        }

        // ---- online softmax (rows fully warp-private; quad reductions) ----
        float mx0 = -1e30f, mx1 = -1e30f;
        #pragma unroll
        for (int j = 0; j < 8; j++) {
            mx0 = fmaxf(mx0, fmaxf(S[j][0], S[j][1]));
            mx1 = fmaxf(mx1, fmaxf(S[j][2], S[j][3]));
        }
        mx0 = fmaxf(mx0, __shfl_xor_sync(0xffffffffu, mx0, 1));
        mx0 = fmaxf(mx0, __shfl_xor_sync(0xffffffffu, mx0, 2));
        mx1 = fmaxf(mx1, __shfl_xor_sync(0xffffffffu, mx1, 1));
        mx1 = fmaxf(mx1, __shfl_xor_sync(0xffffffffu, mx1, 2));
        const float mn0 = fmaxf(mr0, mx0), mn1 = fmaxf(mr1, mx1);
        const float sc0 = __expf(mr0 - mn0), sc1 = __expf(mr1 - mn1);
        mr0 = mn0; mr1 = mn1;

        float s0 = 0.f, s1 = 0.f;
        #pragma unroll
        for (int j = 0; j < 8; j++) {
            S[j][0] = __expf(S[j][0] - mn0); s0 += S[j][0];
            S[j][1] = __expf(S[j][1] - mn0); s0 += S[j][1];
            S[j][2] = __expf(S[j][2] - mn1); s1 += S[j][2];
            S[j][3] = __expf(S[j][3] - mn1); s1 += S[j][3];
        }
        s0 += __shfl_xor_sync(0xffffffffu, s0, 1);
        s0 += __shfl_xor_sync(0xffffffffu, s0, 2);
        s1 += __shfl_xor_sync(0xffffffffu, s1, 1);
        s1 += __shfl_xor_sync(0xffffffffu, s1, 2);
        lr0 = lr0 * sc0 + s0;
        lr1 = lr1 * sc1 + s1;

        #pragma unroll
        for (int j = 0; j < 16; j++) {
            O[j][0] *= sc0; O[j][1] *= sc0;
            O[j][2] *= sc1; O[j][3] *= sc1;
        }

        // ---- O += P V : P single-f16 fragments, V hi/lo split (2-term) ----
        #pragma unroll
        for (int j = 0; j < 4; j++) {               // key k-steps (16 keys)
            uint32_t ph[4];
            ph[0] = packh2(S[2*j][0],   S[2*j][1]);
            ph[1] = packh2(S[2*j][2],   S[2*j][3]);
            ph[2] = packh2(S[2*j+1][0], S[2*j+1][1]);
            ph[3] = packh2(S[2*j+1][2], S[2*j+1][3]);
            #pragma unroll
            for (int dp = 0; dp < 8; dp++) {        // d n-pairs (16 cols)
                uint32_t bh[4], bl[4];
                ldsm_x4_t(bh, a_v_hi + j * 16 * ROWB + dp * 32);
                ldsm_x4_t(bl, a_v_lo + j * 16 * ROWB + dp * 32);
                MMA(O[2*dp],   ph, bh[0], bh[1]);
                MMA(O[2*dp],   ph, bl[0], bl[1]);
                MMA(O[2*dp+1], ph, bh[2], bh[3]);
                MMA(O[2*dp+1], ph, bl[2], bl[3]);
            }
        }
    }

    // ---- epilogue: normalize and store ----
    const float inv0 = 1.0f / lr0, inv1 = 1.0f / lr1;
    const int r0g = m0 + rb + tq;
    const size_t ob0 = ((size_t)(bb * T_ + r0g) * NH + h) * D_;
    const size_t ob1 = ((size_t)(bb * T_ + r0g + 8) * NH + h) * D_;
    #pragma unroll
    for (int j = 0; j < 16; j++) {
        int col = 8 * j + 2 * tr;
        *(float2*)(Out + ob0 + col) = make_float2(O[j][0] * inv0, O[j][1] * inv0);
        *(float2*)(Out + ob1 + col) = make_float2(O[j][2] * inv1, O[j][3] * inv1);
    }
}

extern "C" void kernel_launch(void* const* d_in, const int* in_sizes, int n_in,
                              void* d_out, int out_size) {
    (void)in_sizes; (void)n_in; (void)out_size;
    const float* Q = (const float*)d_in[0];
    const float* K = (const float*)d_in[1];
    const float* V = (const float*)d_in[2];
    float* O = (float*)d_out;

    cudaFuncSetAttribute(swa_mma_kernel,
                         cudaFuncAttributeMaxDynamicSharedMemorySize, SMEM_BYTES);

    dim3 grid(T_ / BM, NH, B_);   // 32 x 16 x 4 = 2048 CTAs
    swa_mma_kernel<<<grid, NTHREADS, SMEM_BYTES>>>(Q, K, V, O);
}

// round 10
// speedup vs baseline: 4.8775x; 1.0127x over previous
#include <cuda_runtime.h>
#include <cuda_fp16.h>
#include <cstdint>

#define B_   4
#define T_   4096
#define NH   16
#define NKV  8
#define D_   128
#define WIN  1024
#define BM   128
#define BN   64
#define NTHREADS 256

// fp16 tiles, rows padded to 136 elements = 272 bytes (272 mod 128 = 16 ->
// ldmatrix 8-row groups tile the 128B space exactly: conflict-free)
#define ROWB 272
#define QHI_OFF 0                       // 128 x 136 f16 = 34816 B
#define QLO_OFF 34816
#define KHI_OFF 69632                   // 64 x 136 f16 = 17408 B
#define KLO_OFF 87040
#define VHI_OFF 104448
#define VLO_OFF 121856
#define STAGE_K 139264                  // 64 x 128 f32 staging = 32768 B
#define STAGE_V 172032
#define SMEM_BYTES 204800               // < 227 KB -> 1 CTA/SM

__device__ __forceinline__ void ldsm_x4(uint32_t (&r)[4], uint32_t addr) {
    asm volatile("ldmatrix.sync.aligned.m8n8.x4.shared.b16 {%0,%1,%2,%3}, [%4];"
                 : "=r"(r[0]), "=r"(r[1]), "=r"(r[2]), "=r"(r[3]) : "r"(addr));
}
__device__ __forceinline__ void ldsm_x4_t(uint32_t (&r)[4], uint32_t addr) {
    asm volatile("ldmatrix.sync.aligned.m8n8.x4.trans.shared.b16 {%0,%1,%2,%3}, [%4];"
                 : "=r"(r[0]), "=r"(r[1]), "=r"(r[2]), "=r"(r[3]) : "r"(addr));
}
#define MMA(C, A, b0, b1) asm volatile( \
    "mma.sync.aligned.m16n8k16.row.col.f32.f16.f16.f32 " \
    "{%0,%1,%2,%3}, {%4,%5,%6,%7}, {%8,%9}, {%0,%1,%2,%3};" \
    : "+f"((C)[0]), "+f"((C)[1]), "+f"((C)[2]), "+f"((C)[3]) \
    : "r"((A)[0]), "r"((A)[1]), "r"((A)[2]), "r"((A)[3]), "r"(b0), "r"(b1))

#define CPA16(dst, src) asm volatile( \
    "cp.async.cg.shared.global [%0], [%1], 16;" :: "r"(dst), "l"(src))
#define CPA_COMMIT asm volatile("cp.async.commit_group;")
#define CPA_WAIT0  asm volatile("cp.async.wait_group 0;")

__device__ __forceinline__ uint32_t hbits(__half2 v) {
    return *reinterpret_cast<uint32_t*>(&v);
}
__device__ __forceinline__ uint32_t packh2(float x, float y) {
    __half2 h = __floats2half2_rn(x, y);
    return hbits(h);
}
// split a float pair into (hi, lo) packed f16x2
__device__ __forceinline__ void split2h(float x, float y, uint32_t &hi, uint32_t &lo) {
    __half2 h = __floats2half2_rn(x, y);
    float2 g = __half22float2(h);
    __half2 l = __floats2half2_rn(x - g.x, y - g.y);
    hi = hbits(h); lo = hbits(l);
}

__global__ void __launch_bounds__(NTHREADS, 1)
swa_mma_kernel(const float* __restrict__ Q, const float* __restrict__ K,
               const float* __restrict__ V, float* __restrict__ Out)
{
    extern __shared__ char smem[];
    uint32_t sbase;
    asm("{ .reg .u64 t; cvta.to.shared.u64 t, %1; cvt.u32.u64 %0, t; }"
        : "=r"(sbase) : "l"(smem));

    const int tid  = threadIdx.x;
    const int lane = tid & 31;
    const int wid  = tid >> 5;          // 8 warps, warp owns rows [16w, 16w+16)
    const int m0   = blockIdx.x * BM;
    const int h    = blockIdx.y;
    const int bb   = blockIdx.z;
    const int kh   = h >> 1;

    const int rb = wid * 16;
    const int tq = lane >> 2;           // 0..7
    const int tr = lane & 3;            // 0..3

    const int kb0 = (m0 >= WIN) ? ((m0 - WIN) >> 6) : 0;
    const int kbm = (m0 >> 6) + 1;

    // per-thread staging indices (fixed for all tiles)
    const int ld_key = tid >> 5;                 // rows: 8 per pass
    const int ld_d4  = (tid & 31) << 2;          // 16B column chunk
    const size_t kvhead = (size_t)(bb * T_) * (NKV * D_) + (size_t)kh * D_;

    // ---- prefetch first K/V tile into fp32 staging via cp.async ----
    {
        const size_t kvb = kvhead + (size_t)kb0 * BN * (NKV * D_);
        #pragma unroll
        for (int i = 0; i < 8; i++) {
            int key = ld_key + i * 8;
            uint32_t so = (uint32_t)(key * D_ + ld_d4) * 4;
            const size_t g = kvb + (size_t)key * (NKV * D_) + ld_d4;
            CPA16(sbase + STAGE_K + so, K + g);
            CPA16(sbase + STAGE_V + so, V + g);
        }
        CPA_COMMIT;
    }

    // ---- load + split Q tile (128 x 128) while prefetch flies ----
    {
        const size_t qbase = ((size_t)(bb * T_ + m0) * NH + h) * D_;
        #pragma unroll
        for (int i = 0; i < 16; i++) {
            int idx = tid + i * NTHREADS;
            int row = idx >> 5, c4 = (idx & 31) << 2;
            float4 f = *(const float4*)(Q + qbase + (size_t)row * (NH * D_) + c4);
            uint32_t h0, l0, h1, l1;
            split2h(f.x, f.y, h0, l0);
            split2h(f.z, f.w, h1, l1);
            int off = row * ROWB + c4 * 2;
            *(uint2*)(smem + QHI_OFF + off) = make_uint2(h0, h1);
            *(uint2*)(smem + QLO_OFF + off) = make_uint2(l0, l1);
        }
    }

    // ldmatrix base addresses (lane-dependent parts precomputed)
    const uint32_t a_q_hi = sbase + QHI_OFF + (rb + (lane & 15)) * ROWB + ((lane >> 4) << 3) * 2;
    const uint32_t a_q_lo = a_q_hi + (QLO_OFF - QHI_OFF);
    const int k_row = ((lane >> 4) << 3) + (lane & 7);
    const int k_col = (((lane >> 3) & 1) << 3);
    const uint32_t a_k_hi = sbase + KHI_OFF + k_row * ROWB + k_col * 2;
    const uint32_t a_k_lo = a_k_hi + (KLO_OFF - KHI_OFF);
    const int v_row = (((lane >> 3) & 1) << 3) + (lane & 7);
    const int v_col = ((lane >> 4) << 3);
    const uint32_t a_v_hi = sbase + VHI_OFF + v_row * ROWB + v_col * 2;
    const uint32_t a_v_lo = a_v_hi + (VLO_OFF - VHI_OFF);

    // O accumulators: 16 d-tiles x 4 f32  (c0,c1 row R0; c2,c3 row R1)
    float O[16][4];
    #pragma unroll
    for (int j = 0; j < 16; j++)
        #pragma unroll
        for (int e = 0; e < 4; e++) O[j][e] = 0.f;

    float mr0 = -1e29f, mr1 = -1e29f, lr0 = 0.f, lr1 = 0.f;

    for (int kb = kb0; kb <= kbm; kb++) {
        const int n0 = kb * BN;
        // mask needed if any causal violation (max key n0+BN-1 > min query m0)
        // or any window violation (min key n0 dead for max query m0+BM-1):
        const bool need_mask = (n0 >= m0) || (n0 + WIN < m0 + BM);

        // staging for tile kb has landed; previous tile's GEMMs are done
        CPA_WAIT0;
        __syncthreads();

        // ---- split staged fp32 K/V -> f16 hi/lo tiles ----
        #pragma unroll
        for (int i = 0; i < 8; i++) {
            int key = ld_key + i * 8;
            uint32_t so = (uint32_t)(key * D_ + ld_d4) * 4;
            float4 fk = *(const float4*)(smem + STAGE_K + so);
            float4 fv = *(const float4*)(smem + STAGE_V + so);
            int off = key * ROWB + ld_d4 * 2;
            uint32_t h0, l0, h1, l1;
            split2h(fk.x, fk.y, h0, l0);
            split2h(fk.z, fk.w, h1, l1);
            *(uint2*)(smem + KHI_OFF + off) = make_uint2(h0, h1);
            *(uint2*)(smem + KLO_OFF + off) = make_uint2(l0, l1);
            split2h(fv.x, fv.y, h0, l0);
            split2h(fv.z, fv.w, h1, l1);
            *(uint2*)(smem + VHI_OFF + off) = make_uint2(h0, h1);
            *(uint2*)(smem + VLO_OFF + off) = make_uint2(l0, l1);
        }
        __syncthreads();   // staging consumed; hi/lo tiles published

        // ---- prefetch next tile (overlaps with GEMM phase) ----
        if (kb < kbm) {
            const size_t kvb = kvhead + (size_t)(n0 + BN) * (NKV * D_);
            #pragma unroll
            for (int i = 0; i < 8; i++) {
                int key = ld_key + i * 8;
                uint32_t so = (uint32_t)(key * D_ + ld_d4) * 4;
                const size_t g = kvb + (size_t)key * (NKV * D_) + ld_d4;
                CPA16(sbase + STAGE_K + so, K + g);
                CPA16(sbase + STAGE_V + so, V + g);
            }
            CPA_COMMIT;
        }

        // ---- S = Q K^T : 16 rows x 64 keys per warp, 3-MMA f16 split ----
        // Term-major issue order: each accumulator revisited only after 8
        // independent MMAs (hides HMMA latency instead of serializing on C).
        float S[8][4];
        #pragma unroll
        for (int j = 0; j < 8; j++)
            #pragma unroll
            for (int e = 0; e < 4; e++) S[j][e] = 0.f;

        #pragma unroll
        for (int ks = 0; ks < 8; ks++) {            // k = 16*ks over d=128
            uint32_t ah[4], al[4], bh[4][4], bl[4][4];
            ldsm_x4(ah, a_q_hi + ks * 32);
            ldsm_x4(al, a_q_lo + ks * 32);
            #pragma unroll
            for (int np = 0; np < 4; np++)
                ldsm_x4(bh[np], a_k_hi + np * 16 * ROWB + ks * 32);
            #pragma unroll
            for (int np = 0; np < 4; np++) {        // term 1: Qhi * Khi
                MMA(S[2*np],   ah, bh[np][0], bh[np][1]);
                MMA(S[2*np+1], ah, bh[np][2], bh[np][3]);
            }
            #pragma unroll
            for (int np = 0; np < 4; np++) {        // term 2: Qlo * Khi
                MMA(S[2*np],   al, bh[np][0], bh[np][1]);
                MMA(S[2*np+1], al, bh[np][2], bh[np][3]);
            }
            #pragma unroll
            for (int np = 0; np < 4; np++)
                ldsm_x4(bl[np], a_k_lo + np * 16 * ROWB + ks * 32);
            #pragma unroll
            for (int np = 0; np < 4; np++) {        // term 3: Qhi * Klo
                MMA(S[2*np],   ah, bl[np][0], bl[np][1]);
                MMA(S[2*np+1], ah, bl[np][2], bl[np][3]);
            }
        }

        if (need_mask) {
            const int q0 = m0 + rb + tq, q1 = q0 + 8;
            #pragma unroll
            for (int j = 0; j < 8; j++) {
                #pragma unroll
                for (int e = 0; e < 2; e++) {
                    int kp = n0 + 8 * j + 2 * tr + e;
                    if (kp > q0 || kp + WIN <= q0) S[j][e]     = -1e30f;
                    if (kp > q1 || kp + WIN <= q1) S[j][2 + e] = -1e30f;
                }
            }
        }

        // ---- online softmax (rows fully warp-private; quad reductions) ----
        float mx0 = -1e30f, mx1 = -1e30f;
        #pragma unroll
        for (int j = 0; j < 8; j++) {
            mx0 = fmaxf(mx0, fmaxf(S[j][0], S[j][1]));
            mx1 = fmaxf(mx1, fmaxf(S[j][2], S[j][3]));
        }
        mx0 = fmaxf(mx0, __shfl_xor_sync(0xffffffffu, mx0, 1));
        mx0 = fmaxf(mx0, __shfl_xor_sync(0xffffffffu, mx0, 2));
        mx1 = fmaxf(mx1, __shfl_xor_sync(0xffffffffu, mx1, 1));
        mx1 = fmaxf(mx1, __shfl_xor_sync(0xffffffffu, mx1, 2));
        const float mn0 = fmaxf(mr0, mx0), mn1 = fmaxf(mr1, mx1);
        const float sc0 = __expf(mr0 - mn0), sc1 = __expf(mr1 - mn1);
        mr0 = mn0; mr1 = mn1;

        float s0 = 0.f, s1 = 0.f;
        #pragma unroll
        for (int j = 0; j < 8; j++) {
            S[j][0] = __expf(S[j][0] - mn0); s0 += S[j][0];
            S[j][1] = __expf(S[j][1] - mn0); s0 += S[j][1];
            S[j][2] = __expf(S[j][2] - mn1); s1 += S[j][2];
            S[j][3] = __expf(S[j][3] - mn1); s1 += S[j][3];
        }
        s0 += __shfl_xor_sync(0xffffffffu, s0, 1);
        s0 += __shfl_xor_sync(0xffffffffu, s0, 2);
        s1 += __shfl_xor_sync(0xffffffffu, s1, 1);
        s1 += __shfl_xor_sync(0xffffffffu, s1, 2);
        lr0 = lr0 * sc0 + s0;
        lr1 = lr1 * sc1 + s1;

        #pragma unroll
        for (int j = 0; j < 16; j++) {
            O[j][0] *= sc0; O[j][1] *= sc0;
            O[j][2] *= sc1; O[j][3] *= sc1;
        }

        // ---- O += P V : P single-f16, V hi/lo (2-term), term-major order ----
        #pragma unroll
        for (int j = 0; j < 4; j++) {               // key k-steps (16 keys)
            uint32_t ph[4];
            ph[0] = packh2(S[2*j][0],   S[2*j][1]);
            ph[1] = packh2(S[2*j][2],   S[2*j][3]);
            ph[2] = packh2(S[2*j+1][0], S[2*j+1][1]);
            ph[3] = packh2(S[2*j+1][2], S[2*j+1][3]);
            uint32_t bv[8][4];
            #pragma unroll
            for (int dp = 0; dp < 8; dp++)
                ldsm_x4_t(bv[dp], a_v_hi + j * 16 * ROWB + dp * 32);
            #pragma unroll
            for (int dp = 0; dp < 8; dp++) {        // term 1: P * Vhi
                MMA(O[2*dp],   ph, bv[dp][0], bv[dp][1]);
                MMA(O[2*dp+1], ph, bv[dp][2], bv[dp][3]);
            }
            #pragma unroll
            for (int dp = 0; dp < 8; dp++)
                ldsm_x4_t(bv[dp], a_v_lo + j * 16 * ROWB + dp * 32);
            #pragma unroll
            for (int dp = 0; dp < 8; dp++) {        // term 2: P * Vlo
                MMA(O[2*dp],   ph, bv[dp][0], bv[dp][1]);
                MMA(O[2*dp+1], ph, bv[dp][2], bv[dp][3]);
            }
        }
    }

    // ---- epilogue: normalize and store ----
    const float inv0 = 1.0f / lr0, inv1 = 1.0f / lr1;
    const int r0g = m0 + rb + tq;
    const size_t ob0 = ((size_t)(bb * T_ + r0g) * NH + h) * D_;
    const size_t ob1 = ((size_t)(bb * T_ + r0g + 8) * NH + h) * D_;
    #pragma unroll
    for (int j = 0; j < 16; j++) {
        int col = 8 * j + 2 * tr;
        *(float2*)(Out + ob0 + col) = make_float2(O[j][0] * inv0, O[j][1] * inv0);
        *(float2*)(Out + ob1 + col) = make_float2(O[j][2] * inv1, O[j][3] * inv1);
    }
}

extern "C" void kernel_launch(void* const* d_in, const int* in_sizes, int n_in,
                              void* d_out, int out_size) {
    (void)in_sizes; (void)n_in; (void)out_size;
    const float* Q = (const float*)d_in[0];
    const float* K = (const float*)d_in[1];
    const float* V = (const float*)d_in[2];
    float* O = (float*)d_out;

    cudaFuncSetAttribute(swa_mma_kernel,
                         cudaFuncAttributeMaxDynamicSharedMemorySize, SMEM_BYTES);

    dim3 grid(T_ / BM, NH, B_);   // 32 x 16 x 4 = 2048 CTAs
    swa_mma_kernel<<<grid, NTHREADS, SMEM_BYTES>>>(Q, K, V, O);
}

// round 11
// speedup vs baseline: 5.5870x; 1.1455x over previous
#include <cuda_runtime.h>
#include <cuda_fp16.h>
#include <cstdint>

#define B_   4
#define T_   4096
#define NH   16
#define NKV  8
#define D_   128
#define WIN  1024
#define BM   64
#define BN   64
#define NTHREADS 128

// fp16 tiles, rows padded to 136 elements = 272 bytes (272 mod 128 = 16 ->
// ldmatrix 8-row groups tile the 128B space exactly: conflict-free)
#define ROWB 272
#define QHI_OFF 0                       // 64 x 136 f16 = 17408 B
#define QLO_OFF 17408
#define KHI_OFF 34816
#define KLO_OFF 52224
#define VHI_OFF 69632                   // V kept single-fp16 (no lo split)
#define SMEM_BYTES 87040                // 2 CTAs/SM (174 KB < 227 KB)

__device__ __forceinline__ void ldsm_x4(uint32_t (&r)[4], uint32_t addr) {
    asm volatile("ldmatrix.sync.aligned.m8n8.x4.shared.b16 {%0,%1,%2,%3}, [%4];"
                 : "=r"(r[0]), "=r"(r[1]), "=r"(r[2]), "=r"(r[3]) : "r"(addr));
}
__device__ __forceinline__ void ldsm_x4_t(uint32_t (&r)[4], uint32_t addr) {
    asm volatile("ldmatrix.sync.aligned.m8n8.x4.trans.shared.b16 {%0,%1,%2,%3}, [%4];"
                 : "=r"(r[0]), "=r"(r[1]), "=r"(r[2]), "=r"(r[3]) : "r"(addr));
}
#define MMA(C, A, b0, b1) asm volatile( \
    "mma.sync.aligned.m16n8k16.row.col.f32.f16.f16.f32 " \
    "{%0,%1,%2,%3}, {%4,%5,%6,%7}, {%8,%9}, {%0,%1,%2,%3};" \
    : "+f"((C)[0]), "+f"((C)[1]), "+f"((C)[2]), "+f"((C)[3]) \
    : "r"((A)[0]), "r"((A)[1]), "r"((A)[2]), "r"((A)[3]), "r"(b0), "r"(b1))

__device__ __forceinline__ uint32_t hbits(__half2 v) {
    return *reinterpret_cast<uint32_t*>(&v);
}
__device__ __forceinline__ uint32_t packh2(float x, float y) {
    __half2 h = __floats2half2_rn(x, y);
    return hbits(h);
}
// split a float pair into (hi, lo) packed f16x2
__device__ __forceinline__ void split2h(float x, float y, uint32_t &hi, uint32_t &lo) {
    __half2 h = __floats2half2_rn(x, y);
    float2 g = __half22float2(h);
    __half2 l = __floats2half2_rn(x - g.x, y - g.y);
    hi = hbits(h); lo = hbits(l);
}

__global__ void __launch_bounds__(NTHREADS, 2)
swa_mma_kernel(const float* __restrict__ Q, const float* __restrict__ K,
               const float* __restrict__ V, float* __restrict__ Out)
{
    extern __shared__ char smem[];
    uint32_t sbase;
    asm("{ .reg .u64 t; cvta.to.shared.u64 t, %1; cvt.u32.u64 %0, t; }"
        : "=r"(sbase) : "l"(smem));

    const int tid  = threadIdx.x;
    const int lane = tid & 31;
    const int wid  = tid >> 5;          // 4 warps, warp owns rows [16w, 16w+16)
    const int m0   = blockIdx.x * BM;
    const int h    = blockIdx.y;
    const int bb   = blockIdx.z;
    const int kh   = h >> 1;

    const int rb = wid * 16;
    const int tq = lane >> 2;           // 0..7
    const int tr = lane & 3;            // 0..3

    const int kb0 = (m0 >= WIN) ? ((m0 - WIN) >> 6) : 0;
    const int kbm = m0 >> 6;

    // ---- load + split Q tile (64 x 128) ----
    {
        const size_t qbase = ((size_t)(bb * T_ + m0) * NH + h) * D_;
        #pragma unroll
        for (int i = 0; i < 16; i++) {
            int idx = tid + i * NTHREADS;            // 2048 float4s
            int row = idx >> 5, c4 = (idx & 31) << 2;
            float4 f = *(const float4*)(Q + qbase + (size_t)row * (NH * D_) + c4);
            uint32_t h0, l0, h1, l1;
            split2h(f.x, f.y, h0, l0);
            split2h(f.z, f.w, h1, l1);
            int off = row * ROWB + c4 * 2;
            *(uint2*)(smem + QHI_OFF + off) = make_uint2(h0, h1);
            *(uint2*)(smem + QLO_OFF + off) = make_uint2(l0, l1);
        }
    }

    // ldmatrix base addresses (lane-dependent parts precomputed)
    const uint32_t a_q_hi = sbase + QHI_OFF + (rb + (lane & 15)) * ROWB + ((lane >> 4) << 3) * 2;
    const uint32_t a_q_lo = a_q_hi + (QLO_OFF - QHI_OFF);
    const int k_row = ((lane >> 4) << 3) + (lane & 7);
    const int k_col = (((lane >> 3) & 1) << 3);
    const uint32_t a_k_hi = sbase + KHI_OFF + k_row * ROWB + k_col * 2;
    const uint32_t a_k_lo = a_k_hi + (KLO_OFF - KHI_OFF);
    const int v_row = (((lane >> 3) & 1) << 3) + (lane & 7);
    const int v_col = ((lane >> 4) << 3);
    const uint32_t a_v_hi = sbase + VHI_OFF + v_row * ROWB + v_col * 2;

    // O accumulators: 16 d-tiles x 4 f32  (c0,c1 row R0; c2,c3 row R1)
    float O[16][4];
    #pragma unroll
    for (int j = 0; j < 16; j++)
        #pragma unroll
        for (int e = 0; e < 4; e++) O[j][e] = 0.f;

    float mr0 = -1e29f, mr1 = -1e29f, lr0 = 0.f, lr1 = 0.f;

    const size_t kvhead = (size_t)(bb * T_) * (NKV * D_) + (size_t)kh * D_;

    for (int kb = kb0; kb <= kbm; kb++) {
        const int n0 = kb * BN;
        // mask needed if any causal violation (max key n0+BN-1 > min query m0)
        // or any window violation (min key n0 dead for max query m0+BM-1):
        const bool need_mask = (n0 >= m0) || (n0 + WIN < m0 + BM);

        __syncthreads();   // previous tile's GEMMs done; safe to overwrite K/V
        // ---- load + split K (hi/lo) and convert V (hi only) ----
        {
            const size_t kvb = kvhead + (size_t)n0 * (NKV * D_);
            #pragma unroll
            for (int i = 0; i < 16; i++) {
                int idx = tid + i * NTHREADS;
                int key = idx >> 5, d4 = (idx & 31) << 2;
                size_t g = kvb + (size_t)key * (NKV * D_) + d4;
                float4 fk = *(const float4*)(K + g);
                float4 fv = *(const float4*)(V + g);
                int off = key * ROWB + d4 * 2;
                uint32_t h0, l0, h1, l1;
                split2h(fk.x, fk.y, h0, l0);
                split2h(fk.z, fk.w, h1, l1);
                *(uint2*)(smem + KHI_OFF + off) = make_uint2(h0, h1);
                *(uint2*)(smem + KLO_OFF + off) = make_uint2(l0, l1);
                h0 = packh2(fv.x, fv.y);
                h1 = packh2(fv.z, fv.w);
                *(uint2*)(smem + VHI_OFF + off) = make_uint2(h0, h1);
            }
        }
        __syncthreads();

        // ---- S = Q K^T : 16 rows x 64 keys per warp, 3-MMA f16 split ----
        float S[8][4];
        #pragma unroll
        for (int j = 0; j < 8; j++)
            #pragma unroll
            for (int e = 0; e < 4; e++) S[j][e] = 0.f;

        #pragma unroll
        for (int ks = 0; ks < 8; ks++) {            // k = 16*ks over d=128
            uint32_t ah[4], al[4], bh[4][4], bl[4][4];
            ldsm_x4(ah, a_q_hi + ks * 32);
            ldsm_x4(al, a_q_lo + ks * 32);
            #pragma unroll
            for (int np = 0; np < 4; np++)
                ldsm_x4(bh[np], a_k_hi + np * 16 * ROWB + ks * 32);
            #pragma unroll
            for (int np = 0; np < 4; np++) {        // term 1: Qhi * Khi
                MMA(S[2*np],   ah, bh[np][0], bh[np][1]);
                MMA(S[2*np+1], ah, bh[np][2], bh[np][3]);
            }
            #pragma unroll
            for (int np = 0; np < 4; np++) {        // term 2: Qlo * Khi
                MMA(S[2*np],   al, bh[np][0], bh[np][1]);
                MMA(S[2*np+1], al, bh[np][2], bh[np][3]);
            }
            #pragma unroll
            for (int np = 0; np < 4; np++)
                ldsm_x4(bl[np], a_k_lo + np * 16 * ROWB + ks * 32);
            #pragma unroll
            for (int np = 0; np < 4; np++) {        // term 3: Qhi * Klo
                MMA(S[2*np],   ah, bl[np][0], bl[np][1]);
                MMA(S[2*np+1], ah, bl[np][2], bl[np][3]);
            }
        }

        if (need_mask) {
            const int q0 = m0 + rb + tq, q1 = q0 + 8;
            #pragma unroll
            for (int j = 0; j < 8; j++) {
                #pragma unroll
                for (int e = 0; e < 2; e++) {
                    int kp = n0 + 8 * j + 2 * tr + e;
                    if (kp > q0 || kp + WIN <= q0) S[j][e]     = -1e30f;
                    if (kp > q1 || kp + WIN <= q1) S[j][2 + e] = -1e30f;
                }
            }
        }

        // ---- online softmax (rows fully warp-private; quad reductions) ----
        float mx0 = -1e30f, mx1 = -1e30f;
        #pragma unroll
        for (int j = 0; j < 8; j++) {
            mx0 = fmaxf(mx0, fmaxf(S[j][0], S[j][1]));
            mx1 = fmaxf(mx1, fmaxf(S[j][2], S[j][3]));
        }
        mx0 = fmaxf(mx0, __shfl_xor_sync(0xffffffffu, mx0, 1));
        mx0 = fmaxf(mx0, __shfl_xor_sync(0xffffffffu, mx0, 2));
        mx1 = fmaxf(mx1, __shfl_xor_sync(0xffffffffu, mx1, 1));
        mx1 = fmaxf(mx1, __shfl_xor_sync(0xffffffffu, mx1, 2));
        const float mn0 = fmaxf(mr0, mx0), mn1 = fmaxf(mr1, mx1);
        const float sc0 = __expf(mr0 - mn0), sc1 = __expf(mr1 - mn1);
        mr0 = mn0; mr1 = mn1;

        float s0 = 0.f, s1 = 0.f;
        #pragma unroll
        for (int j = 0; j < 8; j++) {
            S[j][0] = __expf(S[j][0] - mn0); s0 += S[j][0];
            S[j][1] = __expf(S[j][1] - mn0); s0 += S[j][1];
            S[j][2] = __expf(S[j][2] - mn1); s1 += S[j][2];
            S[j][3] = __expf(S[j][3] - mn1); s1 += S[j][3];
        }
        s0 += __shfl_xor_sync(0xffffffffu, s0, 1);
        s0 += __shfl_xor_sync(0xffffffffu, s0, 2);
        s1 += __shfl_xor_sync(0xffffffffu, s1, 1);
        s1 += __shfl_xor_sync(0xffffffffu, s1, 2);
        lr0 = lr0 * sc0 + s0;
        lr1 = lr1 * sc1 + s1;

        #pragma unroll
        for (int j = 0; j < 16; j++) {
            O[j][0] *= sc0; O[j][1] *= sc0;
            O[j][2] *= sc1; O[j][3] *= sc1;
        }

        // ---- O += P V : P single-f16, V single-f16 (1 MMA per pair) ----
        #pragma unroll
        for (int j = 0; j < 4; j++) {               // key k-steps (16 keys)
            uint32_t ph[4];
            ph[0] = packh2(S[2*j][0],   S[2*j][1]);
            ph[1] = packh2(S[2*j][2],   S[2*j][3]);
            ph[2] = packh2(S[2*j+1][0], S[2*j+1][1]);
            ph[3] = packh2(S[2*j+1][2], S[2*j+1][3]);
            uint32_t bv[8][4];
            #pragma unroll
            for (int dp = 0; dp < 8; dp++)
                ldsm_x4_t(bv[dp], a_v_hi + j * 16 * ROWB + dp * 32);
            #pragma unroll
            for (int dp = 0; dp < 8; dp++) {
                MMA(O[2*dp],   ph, bv[dp][0], bv[dp][1]);
                MMA(O[2*dp+1], ph, bv[dp][2], bv[dp][3]);
            }
        }
    }

    // ---- epilogue: normalize and store ----
    const float inv0 = 1.0f / lr0, inv1 = 1.0f / lr1;
    const int r0g = m0 + rb + tq;
    const size_t ob0 = ((size_t)(bb * T_ + r0g) * NH + h) * D_;
    const size_t ob1 = ((size_t)(bb * T_ + r0g + 8) * NH + h) * D_;
    #pragma unroll
    for (int j = 0; j < 16; j++) {
        int col = 8 * j + 2 * tr;
        *(float2*)(Out + ob0 + col) = make_float2(O[j][0] * inv0, O[j][1] * inv0);
        *(float2*)(Out + ob1 + col) = make_float2(O[j][2] * inv1, O[j][3] * inv1);
    }
}

extern "C" void kernel_launch(void* const* d_in, const int* in_sizes, int n_in,
                              void* d_out, int out_size) {
    (void)in_sizes; (void)n_in; (void)out_size;
    const float* Q = (const float*)d_in[0];
    const float* K = (const float*)d_in[1];
    const float* V = (const float*)d_in[2];
    float* O = (float*)d_out;

    cudaFuncSetAttribute(swa_mma_kernel,
                         cudaFuncAttributeMaxDynamicSharedMemorySize, SMEM_BYTES);

    dim3 grid(T_ / BM, NH, B_);   // 64 x 16 x 4 = 4096 CTAs
    swa_mma_kernel<<<grid, NTHREADS, SMEM_BYTES>>>(Q, K, V, O);
}

// round 12
// speedup vs baseline: 5.5994x; 1.0022x over previous
#include <cuda_runtime.h>
#include <cuda_fp16.h>
#include <cstdint>

#define B_   4
#define T_   4096
#define NH   16
#define NKV  8
#define D_   128
#define WIN  1024
#define BM   64
#define BN   64
#define NTHREADS 128

// fp16 tiles, rows padded to 136 elements = 272 bytes (272 mod 128 = 16 ->
// ldmatrix 8-row groups tile the 128B space exactly: conflict-free)
#define ROWB 272
#define QHI_OFF 0                       // 64 x 136 f16 = 17408 B
#define QLO_OFF 17408
#define KHI_OFF 34816
#define KLO_OFF 52224
#define VHI_OFF 69632                   // V kept single-fp16 (no lo split)
#define SMEM_BYTES 87040                // 2 CTAs/SM (174 KB < 227 KB)

__device__ __forceinline__ void ldsm_x4(uint32_t (&r)[4], uint32_t addr) {
    asm volatile("ldmatrix.sync.aligned.m8n8.x4.shared.b16 {%0,%1,%2,%3}, [%4];"
                 : "=r"(r[0]), "=r"(r[1]), "=r"(r[2]), "=r"(r[3]) : "r"(addr));
}
__device__ __forceinline__ void ldsm_x4_t(uint32_t (&r)[4], uint32_t addr) {
    asm volatile("ldmatrix.sync.aligned.m8n8.x4.trans.shared.b16 {%0,%1,%2,%3}, [%4];"
                 : "=r"(r[0]), "=r"(r[1]), "=r"(r[2]), "=r"(r[3]) : "r"(addr));
}
#define MMA(C, A, b0, b1) asm volatile( \
    "mma.sync.aligned.m16n8k16.row.col.f32.f16.f16.f32 " \
    "{%0,%1,%2,%3}, {%4,%5,%6,%7}, {%8,%9}, {%0,%1,%2,%3};" \
    : "+f"((C)[0]), "+f"((C)[1]), "+f"((C)[2]), "+f"((C)[3]) \
    : "r"((A)[0]), "r"((A)[1]), "r"((A)[2]), "r"((A)[3]), "r"(b0), "r"(b1))

__device__ __forceinline__ uint32_t hbits(__half2 v) {
    return *reinterpret_cast<uint32_t*>(&v);
}
__device__ __forceinline__ uint32_t packh2(float x, float y) {
    __half2 h = __floats2half2_rn(x, y);
    return hbits(h);
}
// split a float pair into (hi, lo) packed f16x2
__device__ __forceinline__ void split2h(float x, float y, uint32_t &hi, uint32_t &lo) {
    __half2 h = __floats2half2_rn(x, y);
    float2 g = __half22float2(h);
    __half2 l = __floats2half2_rn(x - g.x, y - g.y);
    hi = hbits(h); lo = hbits(l);
}

__global__ void __launch_bounds__(NTHREADS, 2)
swa_mma_kernel(const float* __restrict__ Q, const float* __restrict__ K,
               const float* __restrict__ V, float* __restrict__ Out)
{
    extern __shared__ char smem[];
    uint32_t sbase;
    asm("{ .reg .u64 t; cvta.to.shared.u64 t, %1; cvt.u32.u64 %0, t; }"
        : "=r"(sbase) : "l"(smem));

    const int tid  = threadIdx.x;
    const int lane = tid & 31;
    const int wid  = tid >> 5;          // 4 warps, warp owns rows [16w, 16w+16)
    const int m0   = blockIdx.x * BM;
    const int h    = blockIdx.y;
    const int bb   = blockIdx.z;
    const int kh   = h >> 1;

    const int rb = wid * 16;
    const int tq = lane >> 2;           // 0..7
    const int tr = lane & 3;            // 0..3

    const int kb0 = (m0 >= WIN) ? ((m0 - WIN) >> 6) : 0;
    const int kbm = m0 >> 6;

    // ---- load + split Q tile (64 x 128) ----
    {
        const size_t qbase = ((size_t)(bb * T_ + m0) * NH + h) * D_;
        #pragma unroll
        for (int i = 0; i < 16; i++) {
            int idx = tid + i * NTHREADS;            // 2048 float4s
            int row = idx >> 5, c4 = (idx & 31) << 2;
            float4 f = *(const float4*)(Q + qbase + (size_t)row * (NH * D_) + c4);
            uint32_t h0, l0, h1, l1;
            split2h(f.x, f.y, h0, l0);
            split2h(f.z, f.w, h1, l1);
            int off = row * ROWB + c4 * 2;
            *(uint2*)(smem + QHI_OFF + off) = make_uint2(h0, h1);
            *(uint2*)(smem + QLO_OFF + off) = make_uint2(l0, l1);
        }
    }

    // ldmatrix base addresses (lane-dependent parts precomputed)
    const uint32_t a_q_hi = sbase + QHI_OFF + (rb + (lane & 15)) * ROWB + ((lane >> 4) << 3) * 2;
    const uint32_t a_q_lo = a_q_hi + (QLO_OFF - QHI_OFF);
    const int k_row = ((lane >> 4) << 3) + (lane & 7);
    const int k_col = (((lane >> 3) & 1) << 3);
    const uint32_t a_k_hi = sbase + KHI_OFF + k_row * ROWB + k_col * 2;
    const uint32_t a_k_lo = a_k_hi + (KLO_OFF - KHI_OFF);
    const int v_row = (((lane >> 3) & 1) << 3) + (lane & 7);
    const int v_col = ((lane >> 4) << 3);
    const uint32_t a_v_hi = sbase + VHI_OFF + v_row * ROWB + v_col * 2;

    // O accumulators: 16 d-tiles x 4 f32  (c0,c1 row R0; c2,c3 row R1)
    float O[16][4];
    #pragma unroll
    for (int j = 0; j < 16; j++)
        #pragma unroll
        for (int e = 0; e < 4; e++) O[j][e] = 0.f;

    float mr0 = -1e29f, mr1 = -1e29f, lr0 = 0.f, lr1 = 0.f;

    const size_t kvhead = (size_t)(bb * T_) * (NKV * D_) + (size_t)kh * D_;

    for (int kb = kb0; kb <= kbm; kb++) {
        const int n0 = kb * BN;
        // mask needed if any causal violation (max key n0+BN-1 > min query m0)
        // or any window violation (min key n0 dead for max query m0+BM-1):
        const bool need_mask = (n0 >= m0) || (n0 + WIN < m0 + BM);

        __syncthreads();   // previous tile's GEMMs done; safe to overwrite K/V
        // ---- load + split K (hi/lo) and convert V (hi only) ----
        {
            const size_t kvb = kvhead + (size_t)n0 * (NKV * D_);
            #pragma unroll
            for (int i = 0; i < 16; i++) {
                int idx = tid + i * NTHREADS;
                int key = idx >> 5, d4 = (idx & 31) << 2;
                size_t g = kvb + (size_t)key * (NKV * D_) + d4;
                float4 fk = *(const float4*)(K + g);
                float4 fv = *(const float4*)(V + g);
                int off = key * ROWB + d4 * 2;
                uint32_t h0, l0, h1, l1;
                split2h(fk.x, fk.y, h0, l0);
                split2h(fk.z, fk.w, h1, l1);
                *(uint2*)(smem + KHI_OFF + off) = make_uint2(h0, h1);
                *(uint2*)(smem + KLO_OFF + off) = make_uint2(l0, l1);
                h0 = packh2(fv.x, fv.y);
                h1 = packh2(fv.z, fv.w);
                *(uint2*)(smem + VHI_OFF + off) = make_uint2(h0, h1);
            }
        }
        __syncthreads();

        // ---- S = Q K^T : 16 rows x 64 keys per warp, 3-MMA f16 split ----
        float S[8][4];
        #pragma unroll
        for (int j = 0; j < 8; j++)
            #pragma unroll
            for (int e = 0; e < 4; e++) S[j][e] = 0.f;

        #pragma unroll
        for (int ks = 0; ks < 8; ks++) {            // k = 16*ks over d=128
            uint32_t ah[4], al[4], bh[4][4], bl[4][4];
            ldsm_x4(ah, a_q_hi + ks * 32);
            ldsm_x4(al, a_q_lo + ks * 32);
            #pragma unroll
            for (int np = 0; np < 4; np++)
                ldsm_x4(bh[np], a_k_hi + np * 16 * ROWB + ks * 32);
            #pragma unroll
            for (int np = 0; np < 4; np++) {        // term 1: Qhi * Khi
                MMA(S[2*np],   ah, bh[np][0], bh[np][1]);
                MMA(S[2*np+1], ah, bh[np][2], bh[np][3]);
            }
            #pragma unroll
            for (int np = 0; np < 4; np++) {        // term 2: Qlo * Khi
                MMA(S[2*np],   al, bh[np][0], bh[np][1]);
                MMA(S[2*np+1], al, bh[np][2], bh[np][3]);
            }
            #pragma unroll
            for (int np = 0; np < 4; np++)
                ldsm_x4(bl[np], a_k_lo + np * 16 * ROWB + ks * 32);
            #pragma unroll
            for (int np = 0; np < 4; np++) {        // term 3: Qhi * Klo
                MMA(S[2*np],   ah, bl[np][0], bl[np][1]);
                MMA(S[2*np+1], ah, bl[np][2], bl[np][3]);
            }
        }

        if (need_mask) {
            const int q0 = m0 + rb + tq, q1 = q0 + 8;
            #pragma unroll
            for (int j = 0; j < 8; j++) {
                #pragma unroll
                for (int e = 0; e < 2; e++) {
                    int kp = n0 + 8 * j + 2 * tr + e;
                    if (kp > q0 || kp + WIN <= q0) S[j][e]     = -1e30f;
                    if (kp > q1 || kp + WIN <= q1) S[j][2 + e] = -1e30f;
                }
            }
        }

        // ---- online softmax (rows fully warp-private; quad reductions) ----
        float mx0 = -1e30f, mx1 = -1e30f;
        #pragma unroll
        for (int j = 0; j < 8; j++) {
            mx0 = fmaxf(mx0, fmaxf(S[j][0], S[j][1]));
            mx1 = fmaxf(mx1, fmaxf(S[j][2], S[j][3]));
        }
        mx0 = fmaxf(mx0, __shfl_xor_sync(0xffffffffu, mx0, 1));
        mx0 = fmaxf(mx0, __shfl_xor_sync(0xffffffffu, mx0, 2));
        mx1 = fmaxf(mx1, __shfl_xor_sync(0xffffffffu, mx1, 1));
        mx1 = fmaxf(mx1, __shfl_xor_sync(0xffffffffu, mx1, 2));
        const float mn0 = fmaxf(mr0, mx0), mn1 = fmaxf(mr1, mx1);
        const float sc0 = __expf(mr0 - mn0), sc1 = __expf(mr1 - mn1);
        mr0 = mn0; mr1 = mn1;

        float s0 = 0.f, s1 = 0.f;
        #pragma unroll
        for (int j = 0; j < 8; j++) {
            S[j][0] = __expf(S[j][0] - mn0); s0 += S[j][0];
            S[j][1] = __expf(S[j][1] - mn0); s0 += S[j][1];
            S[j][2] = __expf(S[j][2] - mn1); s1 += S[j][2];
            S[j][3] = __expf(S[j][3] - mn1); s1 += S[j][3];
        }
        s0 += __shfl_xor_sync(0xffffffffu, s0, 1);
        s0 += __shfl_xor_sync(0xffffffffu, s0, 2);
        s1 += __shfl_xor_sync(0xffffffffu, s1, 1);
        s1 += __shfl_xor_sync(0xffffffffu, s1, 2);
        lr0 = lr0 * sc0 + s0;
        lr1 = lr1 * sc1 + s1;

        #pragma unroll
        for (int j = 0; j < 16; j++) {
            O[j][0] *= sc0; O[j][1] *= sc0;
            O[j][2] *= sc1; O[j][3] *= sc1;
        }

        // ---- O += P V : P single-f16, V single-f16 (1 MMA per pair) ----
        #pragma unroll
        for (int j = 0; j < 4; j++) {               // key k-steps (16 keys)
            uint32_t ph[4];
            ph[0] = packh2(S[2*j][0],   S[2*j][1]);
            ph[1] = packh2(S[2*j][2],   S[2*j][3]);
            ph[2] = packh2(S[2*j+1][0], S[2*j+1][1]);
            ph[3] = packh2(S[2*j+1][2], S[2*j+1][3]);
            uint32_t bv[8][4];
            #pragma unroll
            for (int dp = 0; dp < 8; dp++)
                ldsm_x4_t(bv[dp], a_v_hi + j * 16 * ROWB + dp * 32);
            #pragma unroll
            for (int dp = 0; dp < 8; dp++) {
                MMA(O[2*dp],   ph, bv[dp][0], bv[dp][1]);
                MMA(O[2*dp+1], ph, bv[dp][2], bv[dp][3]);
            }
        }
    }

    // ---- epilogue: normalize and store ----
    const float inv0 = 1.0f / lr0, inv1 = 1.0f / lr1;
    const int r0g = m0 + rb + tq;
    const size_t ob0 = ((size_t)(bb * T_ + r0g) * NH + h) * D_;
    const size_t ob1 = ((size_t)(bb * T_ + r0g + 8) * NH + h) * D_;
    #pragma unroll
    for (int j = 0; j < 16; j++) {
        int col = 8 * j + 2 * tr;
        *(float2*)(Out + ob0 + col) = make_float2(O[j][0] * inv0, O[j][1] * inv0);
        *(float2*)(Out + ob1 + col) = make_float2(O[j][2] * inv1, O[j][3] * inv1);
    }
}

extern "C" void kernel_launch(void* const* d_in, const int* in_sizes, int n_in,
                              void* d_out, int out_size) {
    (void)in_sizes; (void)n_in; (void)out_size;
    const float* Q = (const float*)d_in[0];
    const float* K = (const float*)d_in[1];
    const float* V = (const float*)d_in[2];
    float* O = (float*)d_out;

    cudaFuncSetAttribute(swa_mma_kernel,
                         cudaFuncAttributeMaxDynamicSharedMemorySize, SMEM_BYTES);

    dim3 grid(T_ / BM, NH, B_);   // 64 x 16 x 4 = 4096 CTAs
    swa_mma_kernel<<<grid, NTHREADS, SMEM_BYTES>>>(Q, K, V, O);
}